// round 1
// baseline (speedup 1.0000x reference)
#include <cuda_runtime.h>
#include <math.h>

#define NB 4
#define NT 1024
#define CM 256
#define CZ 128
#define NH 8
#define DHD 32

// ---- scratch (device globals; no allocation allowed) ----
__device__ float g_q[(size_t)NB*NH*NT*DHD];
__device__ float g_k[(size_t)NB*NH*NT*DHD];
__device__ float g_v[(size_t)NB*NH*NT*DHD];
__device__ float g_g[(size_t)NB*NH*NT*DHD];
__device__ float g_pb[(size_t)NH*NT*NT];       // [h][i][j]  32 MB
__device__ float g_att[(size_t)NB*NT*CM];      // gated attn out [b*t][256]

// ============================================================
// K1: qkv = x @ Wqkv  (M=4096, K=256, N=1024), scatter to q/k/v/g
// column c = d*32 + kk*8 + h  (inner layout (d, k, h))
// ============================================================
__global__ void __launch_bounds__(256) qkv_kernel(const float* __restrict__ x,
                                                  const float* __restrict__ Wqkv) {
    __shared__ float As[16][68];   // [k][m], padded, float4-aligned rows
    __shared__ float Bs[16][64];   // [k][n]
    const int tid = threadIdx.x;
    const int tx = tid & 15, ty = tid >> 4;
    const int m0 = blockIdx.x * 64;
    const int n0 = blockIdx.y * 64;
    float acc[4][4];
#pragma unroll
    for (int i = 0; i < 4; i++)
#pragma unroll
        for (int j = 0; j < 4; j++) acc[i][j] = 0.f;

    for (int k0 = 0; k0 < CM; k0 += 16) {
#pragma unroll
        for (int r = 0; r < 4; r++) {
            int idx = tid + r * 256;              // 0..1023
            int m = idx >> 4, k = idx & 15;
            As[k][m] = x[(size_t)(m0 + m) * CM + k0 + k];
            int kb = idx >> 6, nb = idx & 63;
            Bs[kb][nb] = Wqkv[(size_t)(k0 + kb) * 1024 + n0 + nb];
        }
        __syncthreads();
#pragma unroll
        for (int k = 0; k < 16; k++) {
            float4 a4 = *(const float4*)&As[k][ty * 4];
            float4 b4 = *(const float4*)&Bs[k][tx * 4];
            float av[4] = {a4.x, a4.y, a4.z, a4.w};
            float bv[4] = {b4.x, b4.y, b4.z, b4.w};
#pragma unroll
            for (int i = 0; i < 4; i++)
#pragma unroll
                for (int j = 0; j < 4; j++)
                    acc[i][j] = fmaf(av[i], bv[j], acc[i][j]);
        }
        __syncthreads();
    }
#pragma unroll
    for (int i = 0; i < 4; i++) {
        int m = m0 + ty * 4 + i;
        int b = m >> 10, t = m & 1023;
#pragma unroll
        for (int j = 0; j < 4; j++) {
            int n = n0 + tx * 4 + j;
            int d = n >> 5, rr = n & 31;
            int kk = rr >> 3, h = rr & 7;
            float* dst = (kk == 0) ? g_q : (kk == 1) ? g_k : (kk == 2) ? g_v : g_g;
            dst[(((size_t)b * NH + h) * NT + t) * DHD + d] = acc[i][j];
        }
    }
}

// ============================================================
// K2: pb[h][i][j] = bias_rep[i][j][:] @ Wb[:,h] + bb[h]
// block = 2 i-rows x 32 j, 256 threads (warp = one h)
// ============================================================
__global__ void __launch_bounds__(256) bias_kernel(const float* __restrict__ bias_rep,
                                                   const float* __restrict__ Wb,
                                                   const float* __restrict__ bb) {
    __shared__ float4 bs4[2][32][32];   // [ii][j][c4], xor-swizzled -> 32 KB
    __shared__ float wbt[8][128];       // Wb transposed [h][c]
    const int tid = threadIdx.x;
    const int i0 = blockIdx.x * 2;
    const int j0 = blockIdx.y * 32;

#pragma unroll
    for (int r = 0; r < 4; r++) {
        int idx = tid + r * 256;        // 0..1023 ; Wb is [c][h]
        wbt[idx & 7][idx >> 3] = Wb[idx];
    }
    const float4* src = (const float4*)bias_rep;
#pragma unroll
    for (int r = 0; r < 8; r++) {
        int p = tid + r * 256;          // 0..2047 float4s
        int ii = p >> 10, q = p & 1023;
        int j = q >> 5, c4 = q & 31;
        bs4[ii][j][c4 ^ (j & 7)] = src[((size_t)(i0 + ii) * NT + j0 + j) * 32 + c4];
    }
    __syncthreads();

    const int h = tid >> 5, j = tid & 31;
    const float4* w4 = (const float4*)wbt[h];
    float a0x = 0, a0y = 0, a0z = 0, a0w = 0;
    float a1x = 0, a1y = 0, a1z = 0, a1w = 0;
#pragma unroll
    for (int c4 = 0; c4 < 32; c4++) {
        float4 w = w4[c4];
        float4 f0 = bs4[0][j][c4 ^ (j & 7)];
        float4 f1 = bs4[1][j][c4 ^ (j & 7)];
        a0x = fmaf(f0.x, w.x, a0x);
        a0y = fmaf(f0.y, w.y, a0y);
        a0z = fmaf(f0.z, w.z, a0z);
        a0w = fmaf(f0.w, w.w, a0w);
        a1x = fmaf(f1.x, w.x, a1x);
        a1y = fmaf(f1.y, w.y, a1y);
        a1z = fmaf(f1.z, w.z, a1z);
        a1w = fmaf(f1.w, w.w, a1w);
    }
    float bbv = bb[h];
    float r0 = ((a0x + a0y) + (a0z + a0w)) + bbv;
    float r1 = ((a1x + a1y) + (a1z + a1w)) + bbv;
    g_pb[((size_t)h * NT + i0) * NT + j0 + j] = r0;
    g_pb[((size_t)h * NT + i0 + 1) * NT + j0 + j] = r1;
}

// ============================================================
// K3: flash-style attention with pair bias + sigmoid gate
// block = one (b,h) x 128 query rows; 1 row per thread
// ============================================================
__global__ void __launch_bounds__(128) attn_kernel() {
    __shared__ float Ks[64 * DHD];  // 8 KB
    __shared__ float Vs[64 * DHD];  // 8 KB
    const int bh = blockIdx.x;
    const int b = bh >> 3, h = bh & 7;
    const int row = threadIdx.x;
    const int t = blockIdx.y * 128 + row;

    const float4* qp = (const float4*)(g_q + ((size_t)bh * NT + t) * DHD);
    float4 q[8];
#pragma unroll
    for (int c = 0; c < 8; c++) q[c] = qp[c];
    float4 acc[8];
#pragma unroll
    for (int c = 0; c < 8; c++) acc[c] = make_float4(0.f, 0.f, 0.f, 0.f);
    float mrow = -1e30f, lsum = 0.f;
    const float scale = 0.17677669529663687f;  // 32^-0.5
    const float* pbrow = g_pb + ((size_t)h * NT + t) * NT;

    for (int jt = 0; jt < NT; jt += 64) {
        const float4* ks = (const float4*)(g_k + ((size_t)bh * NT + jt) * DHD);
        const float4* vs = (const float4*)(g_v + ((size_t)bh * NT + jt) * DHD);
#pragma unroll
        for (int r = 0; r < 4; r++) {
            ((float4*)Ks)[row + r * 128] = ks[row + r * 128];
            ((float4*)Vs)[row + r * 128] = vs[row + r * 128];
        }
        __syncthreads();

        float s[64];
        const float4* pb4 = (const float4*)(pbrow + jt);
#pragma unroll
        for (int j4 = 0; j4 < 16; j4++) {
            float4 pb = pb4[j4];
            float pbv[4] = {pb.x, pb.y, pb.z, pb.w};
#pragma unroll
            for (int jj = 0; jj < 4; jj++) {
                int j = j4 * 4 + jj;
                const float4* kr = (const float4*)(Ks + j * DHD);
                float s0 = 0, s1 = 0, s2 = 0, s3 = 0;
#pragma unroll
                for (int c = 0; c < 8; c++) {
                    float4 kv = kr[c];
                    s0 = fmaf(q[c].x, kv.x, s0);
                    s1 = fmaf(q[c].y, kv.y, s1);
                    s2 = fmaf(q[c].z, kv.z, s2);
                    s3 = fmaf(q[c].w, kv.w, s3);
                }
                s[j] = ((s0 + s1) + (s2 + s3)) * scale + pbv[jj];
            }
        }
        float tmax = mrow;
#pragma unroll
        for (int j = 0; j < 64; j++) tmax = fmaxf(tmax, s[j]);
        float corr = __expf(mrow - tmax);   // first iter: exp(-huge)=0
        mrow = tmax;
        lsum *= corr;
#pragma unroll
        for (int c = 0; c < 8; c++) {
            acc[c].x *= corr; acc[c].y *= corr; acc[c].z *= corr; acc[c].w *= corr;
        }
#pragma unroll
        for (int j = 0; j < 64; j++) {
            float p = __expf(s[j] - mrow);
            lsum += p;
            const float4* vr = (const float4*)(Vs + j * DHD);
#pragma unroll
            for (int c = 0; c < 8; c++) {
                float4 vv = vr[c];
                acc[c].x = fmaf(p, vv.x, acc[c].x);
                acc[c].y = fmaf(p, vv.y, acc[c].y);
                acc[c].z = fmaf(p, vv.z, acc[c].z);
                acc[c].w = fmaf(p, vv.w, acc[c].w);
            }
        }
        __syncthreads();
    }
    float inv = 1.f / lsum;
    const float4* gp = (const float4*)(g_g + ((size_t)bh * NT + t) * DHD);
    float4* op = (float4*)(g_att + ((size_t)(b * NT + t)) * CM + h * DHD);
#pragma unroll
    for (int c = 0; c < 8; c++) {
        float4 gv = gp[c];
        float4 o;
        o.x = acc[c].x * inv * (1.f / (1.f + __expf(-gv.x)));
        o.y = acc[c].y * inv * (1.f / (1.f + __expf(-gv.y)));
        o.z = acc[c].z * inv * (1.f / (1.f + __expf(-gv.z)));
        o.w = acc[c].w * inv * (1.f / (1.f + __expf(-gv.w)));
        op[c] = o;
    }
}

// ============================================================
// K4: out = g_att @ W0  (M=4096, K=256, N=256)
// ============================================================
__global__ void __launch_bounds__(256) out_kernel(const float* __restrict__ W0,
                                                  float* __restrict__ out) {
    __shared__ float As[16][68];
    __shared__ float Bs[16][64];
    const int tid = threadIdx.x;
    const int tx = tid & 15, ty = tid >> 4;
    const int m0 = blockIdx.x * 64;
    const int n0 = blockIdx.y * 64;
    float acc[4][4];
#pragma unroll
    for (int i = 0; i < 4; i++)
#pragma unroll
        for (int j = 0; j < 4; j++) acc[i][j] = 0.f;

    for (int k0 = 0; k0 < CM; k0 += 16) {
#pragma unroll
        for (int r = 0; r < 4; r++) {
            int idx = tid + r * 256;
            int m = idx >> 4, k = idx & 15;
            As[k][m] = g_att[(size_t)(m0 + m) * CM + k0 + k];
            int kb = idx >> 6, nb = idx & 63;
            Bs[kb][nb] = W0[(size_t)(k0 + kb) * CM + n0 + nb];
        }
        __syncthreads();
#pragma unroll
        for (int k = 0; k < 16; k++) {
            float4 a4 = *(const float4*)&As[k][ty * 4];
            float4 b4 = *(const float4*)&Bs[k][tx * 4];
            float av[4] = {a4.x, a4.y, a4.z, a4.w};
            float bv[4] = {b4.x, b4.y, b4.z, b4.w};
#pragma unroll
            for (int i = 0; i < 4; i++)
#pragma unroll
                for (int j = 0; j < 4; j++)
                    acc[i][j] = fmaf(av[i], bv[j], acc[i][j]);
        }
        __syncthreads();
    }
#pragma unroll
    for (int i = 0; i < 4; i++) {
        int m = m0 + ty * 4 + i;
        float4 o = make_float4(acc[i][0], acc[i][1], acc[i][2], acc[i][3]);
        *(float4*)&out[(size_t)m * CM + n0 + tx * 4] = o;
    }
}

// ============================================================
extern "C" void kernel_launch(void* const* d_in, const int* in_sizes, int n_in,
                              void* d_out, int out_size) {
    (void)in_sizes; (void)n_in; (void)out_size;
    const float* x        = (const float*)d_in[0];
    const float* bias_rep = (const float*)d_in[1];
    const float* Wqkv     = (const float*)d_in[2];
    const float* W0       = (const float*)d_in[3];
    const float* Wb       = (const float*)d_in[4];
    const float* bb       = (const float*)d_in[5];
    float* out = (float*)d_out;

    qkv_kernel<<<dim3(64, 16), 256>>>(x, Wqkv);
    bias_kernel<<<dim3(512, 32), 256>>>(bias_rep, Wb, bb);
    attn_kernel<<<dim3(32, 8), 128>>>();
    out_kernel<<<dim3(64, 4), 256>>>(W0, out);
}

// round 2
// speedup vs baseline: 1.6789x; 1.6789x over previous
#include <cuda_runtime.h>
#include <math.h>

#define NB 4
#define NT 1024
#define CM 256
#define CZ 128
#define NH 8
#define DHD 32

// ---- scratch (device globals; no allocation allowed) ----
__device__ float g_q[(size_t)NB*NH*NT*DHD];
__device__ float g_k[(size_t)NB*NH*NT*DHD];
__device__ float g_v[(size_t)NB*NH*NT*DHD];
__device__ float g_g[(size_t)NB*NH*NT*DHD];
__device__ float g_pb[(size_t)NH*NT*NT];       // [h][i][j]  32 MB
__device__ float g_att[(size_t)NB*NT*CM];      // gated attn out [b*t][256]

// ============================================================
// K1: qkv = x @ Wqkv  (M=4096, K=256, N=1024), scatter to q/k/v/g
// 128x64 block tile, 256 threads, 8x4 per-thread (1.5 B/FMA)
// ============================================================
__global__ void __launch_bounds__(256) qkv_kernel(const float* __restrict__ x,
                                                  const float* __restrict__ Wqkv) {
    __shared__ float As[16 * 132];   // [k][m] transposed, padded
    __shared__ float Bs[16 * 68];    // [k][n]
    const int tid = threadIdx.x;
    const int tx = tid & 15, ty = tid >> 4;
    const int m0 = blockIdx.x * 128;
    const int n0 = blockIdx.y * 64;
    float acc[32];
#pragma unroll
    for (int i = 0; i < 32; i++) acc[i] = 0.f;

    for (int k0 = 0; k0 < CM; k0 += 16) {
#pragma unroll
        for (int r = 0; r < 2; r++) {
            int idx = tid + r * 256;            // 0..511
            int m = idx >> 2, kq = (idx & 3) * 4;
            float4 a = *(const float4*)&x[(size_t)(m0 + m) * CM + k0 + kq];
            As[(kq + 0) * 132 + m] = a.x;
            As[(kq + 1) * 132 + m] = a.y;
            As[(kq + 2) * 132 + m] = a.z;
            As[(kq + 3) * 132 + m] = a.w;
        }
        {
            int k = tid >> 4, n4 = (tid & 15) * 4;
            *(float4*)&Bs[k * 68 + n4] =
                *(const float4*)&Wqkv[(size_t)(k0 + k) * 1024 + n0 + n4];
        }
        __syncthreads();
#pragma unroll
        for (int k = 0; k < 16; k++) {
            float4 a0 = *(const float4*)&As[k * 132 + ty * 8];
            float4 a1 = *(const float4*)&As[k * 132 + ty * 8 + 4];
            float4 b  = *(const float4*)&Bs[k * 68 + tx * 4];
            float av[8] = {a0.x, a0.y, a0.z, a0.w, a1.x, a1.y, a1.z, a1.w};
            float bv[4] = {b.x, b.y, b.z, b.w};
#pragma unroll
            for (int i = 0; i < 8; i++)
#pragma unroll
                for (int j = 0; j < 4; j++)
                    acc[i * 4 + j] = fmaf(av[i], bv[j], acc[i * 4 + j]);
        }
        __syncthreads();
    }
#pragma unroll
    for (int i = 0; i < 8; i++) {
        int m = m0 + ty * 8 + i;
        int b = m >> 10, t = m & 1023;
#pragma unroll
        for (int j = 0; j < 4; j++) {
            int n = n0 + tx * 4 + j;
            int d = n >> 5, rr = n & 31;
            int kk = rr >> 3, h = rr & 7;
            float* dst = (kk == 0) ? g_q : (kk == 1) ? g_k : (kk == 2) ? g_v : g_g;
            dst[(((size_t)b * NH + h) * NT + t) * DHD + d] = acc[i * 4 + j];
        }
    }
}

// ============================================================
// K2: pb[h][i][j] = bias_rep[i][j][:] @ Wb[:,h] + bb[h]
// ============================================================
__global__ void __launch_bounds__(256) bias_kernel(const float* __restrict__ bias_rep,
                                                   const float* __restrict__ Wb,
                                                   const float* __restrict__ bb) {
    __shared__ float4 bs4[2][32][32];   // [ii][j][c4], xor-swizzled -> 32 KB
    __shared__ float wbt[8][128];       // Wb transposed [h][c]
    const int tid = threadIdx.x;
    const int i0 = blockIdx.x * 2;
    const int j0 = blockIdx.y * 32;

#pragma unroll
    for (int r = 0; r < 4; r++) {
        int idx = tid + r * 256;        // 0..1023 ; Wb is [c][h]
        wbt[idx & 7][idx >> 3] = Wb[idx];
    }
    const float4* src = (const float4*)bias_rep;
#pragma unroll
    for (int r = 0; r < 8; r++) {
        int p = tid + r * 256;          // 0..2047 float4s
        int ii = p >> 10, q = p & 1023;
        int j = q >> 5, c4 = q & 31;
        bs4[ii][j][c4 ^ (j & 7)] = src[((size_t)(i0 + ii) * NT + j0 + j) * 32 + c4];
    }
    __syncthreads();

    const int h = tid >> 5, j = tid & 31;
    const float4* w4 = (const float4*)wbt[h];
    float a0x = 0, a0y = 0, a0z = 0, a0w = 0;
    float a1x = 0, a1y = 0, a1z = 0, a1w = 0;
#pragma unroll
    for (int c4 = 0; c4 < 32; c4++) {
        float4 w = w4[c4];
        float4 f0 = bs4[0][j][c4 ^ (j & 7)];
        float4 f1 = bs4[1][j][c4 ^ (j & 7)];
        a0x = fmaf(f0.x, w.x, a0x);
        a0y = fmaf(f0.y, w.y, a0y);
        a0z = fmaf(f0.z, w.z, a0z);
        a0w = fmaf(f0.w, w.w, a0w);
        a1x = fmaf(f1.x, w.x, a1x);
        a1y = fmaf(f1.y, w.y, a1y);
        a1z = fmaf(f1.z, w.z, a1z);
        a1w = fmaf(f1.w, w.w, a1w);
    }
    float bbv = bb[h];
    float r0 = ((a0x + a0y) + (a0z + a0w)) + bbv;
    float r1 = ((a1x + a1y) + (a1z + a1w)) + bbv;
    g_pb[((size_t)h * NT + i0) * NT + j0 + j] = r0;
    g_pb[((size_t)h * NT + i0 + 1) * NT + j0 + j] = r1;
}

// ============================================================
// K3: flash attention, GEMM-ified.
// block = (b,h) x 64 q-rows; 128 threads = 8 tx x 16 ty
// per-thread: S microtile 4rows x 8cols, O microtile 4rows x 4d
// ============================================================
__global__ void __launch_bounds__(128, 4) attn_kernel() {
    __shared__ float Qt[32 * 68];   // [d][row], pre-scaled
    __shared__ float Kt[32 * 68];   // [d][col]
    __shared__ float Vs[64 * 32];   // [j][d]
    __shared__ float Ps[64 * 68];   // [j][row], xor-swizzled
    const int bh = blockIdx.x;
    const int b = bh >> 3, h = bh & 7;
    const int i0 = blockIdx.y * 64;
    const int tid = threadIdx.x;
    const int tx = tid & 7, ty = tid >> 3;
    const int ty4 = ty * 4, tx8 = tx * 8, tx4 = tx * 4;
    const float scale = 0.17677669529663687f;  // 32^-0.5

    // stage Q transposed + pre-scaled (once)
    {
        const float* qb = g_q + ((size_t)bh * NT + i0) * DHD;
#pragma unroll
        for (int r = 0; r < 4; r++) {
            int idx = tid + r * 128;           // 0..511
            int row = idx >> 3, d4 = (idx & 7) * 4;
            float4 qv = *(const float4*)&qb[row * DHD + d4];
            Qt[(d4 + 0) * 68 + row] = qv.x * scale;
            Qt[(d4 + 1) * 68 + row] = qv.y * scale;
            Qt[(d4 + 2) * 68 + row] = qv.z * scale;
            Qt[(d4 + 3) * 68 + row] = qv.w * scale;
        }
    }

    float acc[16];
#pragma unroll
    for (int i = 0; i < 16; i++) acc[i] = 0.f;
    float mrow[4] = {-1e30f, -1e30f, -1e30f, -1e30f};
    float lrow[4] = {0.f, 0.f, 0.f, 0.f};

    const float* pbrow = g_pb + (size_t)h * NT * NT + (size_t)(i0 + ty4) * NT;

    for (int jt = 0; jt < NT; jt += 64) {
        __syncthreads();
        // stage K transposed + V
        {
            const float* kb = g_k + ((size_t)bh * NT + jt) * DHD;
            const float* vb = g_v + ((size_t)bh * NT + jt) * DHD;
#pragma unroll
            for (int r = 0; r < 4; r++) {
                int idx = tid + r * 128;
                int row = idx >> 3, d4 = (idx & 7) * 4;
                float4 kv = *(const float4*)&kb[row * DHD + d4];
                Kt[(d4 + 0) * 68 + row] = kv.x;
                Kt[(d4 + 1) * 68 + row] = kv.y;
                Kt[(d4 + 2) * 68 + row] = kv.z;
                Kt[(d4 + 3) * 68 + row] = kv.w;
                *(float4*)&Vs[row * DHD + d4] = *(const float4*)&vb[row * DHD + d4];
            }
        }
        __syncthreads();

        // S = (Q*scale) @ K^T  :  s_[cc*4+i] = S[row ty4+i][col tx8+cc]
        float s_[32];
#pragma unroll
        for (int i = 0; i < 32; i++) s_[i] = 0.f;
#pragma unroll 16
        for (int d = 0; d < 32; d++) {
            float4 qa = *(const float4*)&Qt[d * 68 + ty4];
            float4 k0 = *(const float4*)&Kt[d * 68 + tx8];
            float4 k1 = *(const float4*)&Kt[d * 68 + tx8 + 4];
            float qv[4] = {qa.x, qa.y, qa.z, qa.w};
            float kv[8] = {k0.x, k0.y, k0.z, k0.w, k1.x, k1.y, k1.z, k1.w};
#pragma unroll
            for (int cc = 0; cc < 8; cc++)
#pragma unroll
                for (int i = 0; i < 4; i++)
                    s_[cc * 4 + i] = fmaf(qv[i], kv[cc], s_[cc * 4 + i]);
        }
        // + pair bias
#pragma unroll
        for (int i = 0; i < 4; i++) {
            float4 p0 = *(const float4*)&pbrow[(size_t)i * NT + jt + tx8];
            float4 p1 = *(const float4*)&pbrow[(size_t)i * NT + jt + tx8 + 4];
            s_[0 * 4 + i] += p0.x;  s_[1 * 4 + i] += p0.y;
            s_[2 * 4 + i] += p0.z;  s_[3 * 4 + i] += p0.w;
            s_[4 * 4 + i] += p1.x;  s_[5 * 4 + i] += p1.y;
            s_[6 * 4 + i] += p1.z;  s_[7 * 4 + i] += p1.w;
        }

        // online softmax: row reductions across the 8 tx lanes
        float corr[4];
#pragma unroll
        for (int i = 0; i < 4; i++) {
            float v = s_[i];
#pragma unroll
            for (int cc = 1; cc < 8; cc++) v = fmaxf(v, s_[cc * 4 + i]);
            v = fmaxf(v, __shfl_xor_sync(0xffffffffu, v, 1));
            v = fmaxf(v, __shfl_xor_sync(0xffffffffu, v, 2));
            v = fmaxf(v, __shfl_xor_sync(0xffffffffu, v, 4));
            float mn = fmaxf(mrow[i], v);
            corr[i] = __expf(mrow[i] - mn);
            mrow[i] = mn;
        }
        float rs[4] = {0.f, 0.f, 0.f, 0.f};
#pragma unroll
        for (int cc = 0; cc < 8; cc++) {
            float4 p4;
            p4.x = __expf(s_[cc * 4 + 0] - mrow[0]); rs[0] += p4.x;
            p4.y = __expf(s_[cc * 4 + 1] - mrow[1]); rs[1] += p4.y;
            p4.z = __expf(s_[cc * 4 + 2] - mrow[2]); rs[2] += p4.z;
            p4.w = __expf(s_[cc * 4 + 3] - mrow[3]); rs[3] += p4.w;
            *(float4*)&Ps[(tx8 + cc) * 68 + (ty4 ^ tx4)] = p4;
        }
#pragma unroll
        for (int i = 0; i < 4; i++) {
            float t = rs[i];
            t += __shfl_xor_sync(0xffffffffu, t, 1);
            t += __shfl_xor_sync(0xffffffffu, t, 2);
            t += __shfl_xor_sync(0xffffffffu, t, 4);
            lrow[i] = lrow[i] * corr[i] + t;
            acc[i * 4 + 0] *= corr[i];
            acc[i * 4 + 1] *= corr[i];
            acc[i * 4 + 2] *= corr[i];
            acc[i * 4 + 3] *= corr[i];
        }
        __syncthreads();

        // O += P @ V : per-thread 4 rows x 4 d (d = tx4..tx4+3)
#pragma unroll 16
        for (int j = 0; j < 64; j++) {
            float4 pv = *(const float4*)&Ps[j * 68 + (ty4 ^ (((j >> 3) & 7) << 2))];
            float4 vv = *(const float4*)&Vs[j * DHD + tx4];
            float pp[4] = {pv.x, pv.y, pv.z, pv.w};
            float vl[4] = {vv.x, vv.y, vv.z, vv.w};
#pragma unroll
            for (int i = 0; i < 4; i++)
#pragma unroll
                for (int dd = 0; dd < 4; dd++)
                    acc[i * 4 + dd] = fmaf(pp[i], vl[dd], acc[i * 4 + dd]);
        }
    }

    // epilogue: normalize, gate, scatter into [b*t][256]
#pragma unroll
    for (int i = 0; i < 4; i++) {
        int t = i0 + ty4 + i;
        float inv = 1.f / lrow[i];
        float4 g4 = *(const float4*)&g_g[((size_t)bh * NT + t) * DHD + tx4];
        float4 o;
        o.x = acc[i * 4 + 0] * inv * (1.f / (1.f + __expf(-g4.x)));
        o.y = acc[i * 4 + 1] * inv * (1.f / (1.f + __expf(-g4.y)));
        o.z = acc[i * 4 + 2] * inv * (1.f / (1.f + __expf(-g4.z)));
        o.w = acc[i * 4 + 3] * inv * (1.f / (1.f + __expf(-g4.w)));
        *(float4*)&g_att[((size_t)(b * NT + t)) * CM + h * DHD + tx4] = o;
    }
}

// ============================================================
// K4: out = g_att @ W0  (M=4096, K=256, N=256), 128x64 tile, 8x4/thread
// ============================================================
__global__ void __launch_bounds__(256) out_kernel(const float* __restrict__ W0,
                                                  float* __restrict__ out) {
    __shared__ float As[16 * 132];
    __shared__ float Bs[16 * 68];
    const int tid = threadIdx.x;
    const int tx = tid & 15, ty = tid >> 4;
    const int m0 = blockIdx.x * 128;
    const int n0 = blockIdx.y * 64;
    float acc[32];
#pragma unroll
    for (int i = 0; i < 32; i++) acc[i] = 0.f;

    for (int k0 = 0; k0 < CM; k0 += 16) {
#pragma unroll
        for (int r = 0; r < 2; r++) {
            int idx = tid + r * 256;
            int m = idx >> 2, kq = (idx & 3) * 4;
            float4 a = *(const float4*)&g_att[(size_t)(m0 + m) * CM + k0 + kq];
            As[(kq + 0) * 132 + m] = a.x;
            As[(kq + 1) * 132 + m] = a.y;
            As[(kq + 2) * 132 + m] = a.z;
            As[(kq + 3) * 132 + m] = a.w;
        }
        {
            int k = tid >> 4, n4 = (tid & 15) * 4;
            *(float4*)&Bs[k * 68 + n4] =
                *(const float4*)&W0[(size_t)(k0 + k) * CM + n0 + n4];
        }
        __syncthreads();
#pragma unroll
        for (int k = 0; k < 16; k++) {
            float4 a0 = *(const float4*)&As[k * 132 + ty * 8];
            float4 a1 = *(const float4*)&As[k * 132 + ty * 8 + 4];
            float4 b  = *(const float4*)&Bs[k * 68 + tx * 4];
            float av[8] = {a0.x, a0.y, a0.z, a0.w, a1.x, a1.y, a1.z, a1.w};
            float bv[4] = {b.x, b.y, b.z, b.w};
#pragma unroll
            for (int i = 0; i < 8; i++)
#pragma unroll
                for (int j = 0; j < 4; j++)
                    acc[i * 4 + j] = fmaf(av[i], bv[j], acc[i * 4 + j]);
        }
        __syncthreads();
    }
#pragma unroll
    for (int i = 0; i < 8; i++) {
        int m = m0 + ty * 8 + i;
        float4 o = make_float4(acc[i * 4 + 0], acc[i * 4 + 1],
                               acc[i * 4 + 2], acc[i * 4 + 3]);
        *(float4*)&out[(size_t)m * CM + n0 + tx * 4] = o;
    }
}

// ============================================================
extern "C" void kernel_launch(void* const* d_in, const int* in_sizes, int n_in,
                              void* d_out, int out_size) {
    (void)in_sizes; (void)n_in; (void)out_size;
    const float* x        = (const float*)d_in[0];
    const float* bias_rep = (const float*)d_in[1];
    const float* Wqkv     = (const float*)d_in[2];
    const float* W0       = (const float*)d_in[3];
    const float* Wb       = (const float*)d_in[4];
    const float* bb       = (const float*)d_in[5];
    float* out = (float*)d_out;

    qkv_kernel<<<dim3(32, 16), 256>>>(x, Wqkv);
    bias_kernel<<<dim3(512, 32), 256>>>(bias_rep, Wb, bb);
    attn_kernel<<<dim3(32, 16), 128>>>();
    out_kernel<<<dim3(32, 4), 256>>>(W0, out);
}

// round 3
// speedup vs baseline: 2.8874x; 1.7198x over previous
#include <cuda_runtime.h>
#include <math.h>

#define NB 4
#define NT 1024
#define CM 256
#define NH 8
#define DHD 32
#define MTOT (NB*NT)   // 4096

// ---- scratch (device globals) ----
__device__ float g_qkvT[(size_t)4*CM*MTOT];   // [n=1024][m=4096], n = d*32 + kk*8 + h
__device__ float g_pb[(size_t)NH*NT*NT];      // [h][i*1024+j]  32 MB
__device__ float g_att[(size_t)MTOT*CM];      // [m][h*32+d]

__device__ __forceinline__ unsigned f2tf(float x) {
    unsigned r; asm("cvt.rna.tf32.f32 %0, %1;" : "=r"(r) : "f"(x)); return r;
}
__device__ __forceinline__ void mma8(float* d, unsigned a0, unsigned a1,
                                     unsigned a2, unsigned a3,
                                     unsigned b0, unsigned b1) {
    asm("mma.sync.aligned.m16n8k8.row.col.f32.tf32.tf32.f32 "
        "{%0,%1,%2,%3}, {%4,%5,%6,%7}, {%8,%9}, {%0,%1,%2,%3};"
        : "+f"(d[0]), "+f"(d[1]), "+f"(d[2]), "+f"(d[3])
        : "r"(a0), "r"(a1), "r"(a2), "r"(a3), "r"(b0), "r"(b1));
}

// ============================================================
// K1: qkv = x @ Wqkv -> g_qkvT[n][m]   (M=4096,K=256,N=1024)
// 256 thr, tile 128x64, warps 4(m) x 2(n), per-warp 32x32
// ============================================================
__global__ void __launch_bounds__(256) qkv_kernel(const float* __restrict__ x,
                                                  const float* __restrict__ Wqkv) {
    __shared__ __align__(16) unsigned char smem[64*132*4];  // 33792 B
    unsigned* As = (unsigned*)smem;            // [128][36]
    unsigned* Bs = As + 128*36;                // [32][72]
    float* Ts = (float*)smem;                  // epilogue [64][132]

    const int tid = threadIdx.x;
    const int warp = tid >> 5, lane = tid & 31;
    const int g = lane >> 2, tig = lane & 3;
    const int wm = warp >> 1, wn = warp & 1;
    const int m0 = blockIdx.x * 128, n0 = blockIdx.y * 64;

    float acc[2][4][4];
#pragma unroll
    for (int i = 0; i < 2; i++)
#pragma unroll
        for (int j = 0; j < 4; j++)
#pragma unroll
            for (int c = 0; c < 4; c++) acc[i][j][c] = 0.f;

    for (int k0 = 0; k0 < CM; k0 += 32) {
        __syncthreads();
        {   // stage A: 128 rows x 32 k
            int row = tid >> 1, half = tid & 1;
            const float* src = x + (size_t)(m0 + row) * CM + k0 + half * 16;
            unsigned* dst = As + row * 36 + half * 16;
#pragma unroll
            for (int i = 0; i < 4; i++) {
                float4 v = *(const float4*)(src + i * 4);
                dst[i*4+0] = f2tf(v.x); dst[i*4+1] = f2tf(v.y);
                dst[i*4+2] = f2tf(v.z); dst[i*4+3] = f2tf(v.w);
            }
        }
        {   // stage B: 32 rows x 64 n
#pragma unroll
            for (int p = 0; p < 2; p++) {
                int row = (tid >> 4) + p * 16, c4 = (tid & 15) * 4;
                float4 v = *(const float4*)(Wqkv + (size_t)(k0 + row) * 1024 + n0 + c4);
                unsigned* dst = Bs + row * 72 + c4;
                dst[0] = f2tf(v.x); dst[1] = f2tf(v.y);
                dst[2] = f2tf(v.z); dst[3] = f2tf(v.w);
            }
        }
        __syncthreads();
#pragma unroll
        for (int kc = 0; kc < 4; kc++) {
            unsigned a[2][4];
#pragma unroll
            for (int mt = 0; mt < 2; mt++) {
                int r = wm * 32 + mt * 16;
                a[mt][0] = As[(r + g) * 36 + kc * 8 + tig];
                a[mt][1] = As[(r + g + 8) * 36 + kc * 8 + tig];
                a[mt][2] = As[(r + g) * 36 + kc * 8 + tig + 4];
                a[mt][3] = As[(r + g + 8) * 36 + kc * 8 + tig + 4];
            }
#pragma unroll
            for (int nt = 0; nt < 4; nt++) {
                int c = wn * 32 + nt * 8;
                unsigned b0 = Bs[(kc * 8 + tig) * 72 + c + g];
                unsigned b1 = Bs[(kc * 8 + tig + 4) * 72 + c + g];
                mma8(acc[0][nt], a[0][0], a[0][1], a[0][2], a[0][3], b0, b1);
                mma8(acc[1][nt], a[1][0], a[1][1], a[1][2], a[1][3], b0, b1);
            }
        }
    }
    // epilogue: transpose via smem, coalesced store to g_qkvT[n][m]
    __syncthreads();
#pragma unroll
    for (int mt = 0; mt < 2; mt++) {
        int r = wm * 32 + mt * 16 + g;
#pragma unroll
        for (int nt = 0; nt < 4; nt++) {
            int c = wn * 32 + nt * 8 + 2 * tig;
            Ts[c * 132 + r]           = acc[mt][nt][0];
            Ts[(c + 1) * 132 + r]     = acc[mt][nt][1];
            Ts[c * 132 + r + 8]       = acc[mt][nt][2];
            Ts[(c + 1) * 132 + r + 8] = acc[mt][nt][3];
        }
    }
    __syncthreads();
    {
        int col = tid >> 2, q = tid & 3;
        float* dst = g_qkvT + (size_t)(n0 + col) * MTOT + m0 + q * 32;
        const float* srcT = Ts + col * 132 + q * 32;
#pragma unroll
        for (int i = 0; i < 8; i++)
            *(float4*)(dst + i * 4) = *(const float4*)(srcT + i * 4);
    }
}

// ============================================================
// K2: pb[h][i*1024+j] = bias_rep[i][j][:]@Wb[:,h] + bb[h]
// 128 thr, 64 (i,j)-rows per block, 16 HMMA/warp
// ============================================================
__global__ void __launch_bounds__(128) bias_kernel(const float* __restrict__ bias_rep,
                                                   const float* __restrict__ Wb,
                                                   const float* __restrict__ bb) {
    __shared__ __align__(16) unsigned As[64 * 132];   // 33792 B
    const int tid = threadIdx.x;
    const int w = tid >> 5, lane = tid & 31;
    const int g = lane >> 2, tig = lane & 3;
    const int bi = blockIdx.x;          // i
    const int j0 = blockIdx.y * 64;     // j tile

    // B fragments (Wb [c=128][h=8]) -> registers, tf32
    unsigned wb0[16], wb1[16];
#pragma unroll
    for (int kc = 0; kc < 16; kc++) {
        wb0[kc] = f2tf(__ldg(&Wb[(kc * 8 + tig) * 8 + g]));
        wb1[kc] = f2tf(__ldg(&Wb[(kc * 8 + tig + 4) * 8 + g]));
    }
    float bbv0 = __ldg(&bb[2 * tig]);
    float bbv1 = __ldg(&bb[2 * tig + 1]);

    // stage 64 rows x 128 c
#pragma unroll
    for (int p = 0; p < 16; p++) {
        int idx = tid + p * 128;
        int row = idx >> 5, c4 = (idx & 31) * 4;
        float4 v = *(const float4*)(bias_rep +
                    ((size_t)bi * NT + j0 + row) * 128 + c4);
        unsigned* dst = As + row * 132 + c4;
        dst[0] = f2tf(v.x); dst[1] = f2tf(v.y);
        dst[2] = f2tf(v.z); dst[3] = f2tf(v.w);
    }
    __syncthreads();

    float dd[4] = {0.f, 0.f, 0.f, 0.f};
#pragma unroll
    for (int kc = 0; kc < 16; kc++) {
        unsigned a0 = As[(w * 16 + g) * 132 + kc * 8 + tig];
        unsigned a1 = As[(w * 16 + g + 8) * 132 + kc * 8 + tig];
        unsigned a2 = As[(w * 16 + g) * 132 + kc * 8 + tig + 4];
        unsigned a3 = As[(w * 16 + g + 8) * 132 + kc * 8 + tig + 4];
        mma8(dd, a0, a1, a2, a3, wb0[kc], wb1[kc]);
    }
    size_t m = (size_t)bi * NT + j0 + w * 16 + g;
    g_pb[(size_t)(2 * tig) * (NT * NT)     + m]     = dd[0] + bbv0;
    g_pb[(size_t)(2 * tig + 1) * (NT * NT) + m]     = dd[1] + bbv1;
    g_pb[(size_t)(2 * tig) * (NT * NT)     + m + 8] = dd[2] + bbv0;
    g_pb[(size_t)(2 * tig + 1) * (NT * NT) + m + 8] = dd[3] + bbv1;
}

// ============================================================
// K3: flash attention with pair bias + gate, tf32 HMMA
// 128 thr = 4 warps; block = (b,h) x 64 q-rows
// ============================================================
__global__ void __launch_bounds__(128) attn_kernel() {
    __shared__ __align__(16) unsigned Qs[32 * 72];   // [d][i]
    __shared__ __align__(16) unsigned Ks[32 * 72];   // [d][j]
    __shared__ __align__(16) unsigned Vs[32 * 72];   // [d][j]
    __shared__ __align__(16) unsigned Ps[64 * 68];   // [i][j] tf32

    const int bh = blockIdx.x;
    const int b = bh >> 3, h = bh & 7;
    const int i0 = blockIdx.y * 64;
    const int tid = threadIdx.x;
    const int w = tid >> 5, lane = tid & 31;
    const int g = lane >> 2, tig = lane & 3;
    const float scale = 0.17677669529663687f;  // 32^-0.5

    // stage Q [d][i], pre-scaled
    {
        int d = w * 8 + (lane >> 2);
        int c0 = (lane & 3) * 16;
        const float* src = g_qkvT + (size_t)(d * 32 + h) * MTOT + b * NT + i0 + c0;
        unsigned* dst = Qs + d * 72 + c0;
#pragma unroll
        for (int i = 0; i < 4; i++) {
            float4 v = *(const float4*)(src + i * 4);
            dst[i*4+0] = f2tf(v.x * scale); dst[i*4+1] = f2tf(v.y * scale);
            dst[i*4+2] = f2tf(v.z * scale); dst[i*4+3] = f2tf(v.w * scale);
        }
    }

    float oacc[4][4];
#pragma unroll
    for (int i = 0; i < 4; i++)
#pragma unroll
        for (int c = 0; c < 4; c++) oacc[i][c] = 0.f;
    float mrow0 = -1e30f, mrow1 = -1e30f, lsum0 = 0.f, lsum1 = 0.f;

    const float* pb0 = g_pb + (size_t)h * (NT * NT) + (size_t)(i0 + w * 16 + g) * NT;
    const float* pb1 = pb0 + 8 * NT;

    for (int jt = 0; jt < NT; jt += 64) {
        __syncthreads();
        {   // stage K, V [d][j]
            int d = w * 8 + (lane >> 2);
            int c0 = (lane & 3) * 16;
            const float* ks = g_qkvT + (size_t)(d * 32 + 8 + h) * MTOT + b * NT + jt + c0;
            const float* vs = g_qkvT + (size_t)(d * 32 + 16 + h) * MTOT + b * NT + jt + c0;
            unsigned* kd = Ks + d * 72 + c0;
            unsigned* vd = Vs + d * 72 + c0;
#pragma unroll
            for (int i = 0; i < 4; i++) {
                float4 kv = *(const float4*)(ks + i * 4);
                float4 vv = *(const float4*)(vs + i * 4);
                kd[i*4+0] = f2tf(kv.x); kd[i*4+1] = f2tf(kv.y);
                kd[i*4+2] = f2tf(kv.z); kd[i*4+3] = f2tf(kv.w);
                vd[i*4+0] = f2tf(vv.x); vd[i*4+1] = f2tf(vv.y);
                vd[i*4+2] = f2tf(vv.z); vd[i*4+3] = f2tf(vv.w);
            }
        }
        __syncthreads();

        // S = Q K^T  (8 n-tiles of 8 cols)
        float sa[8][4];
#pragma unroll
        for (int nt = 0; nt < 8; nt++)
#pragma unroll
            for (int c = 0; c < 4; c++) sa[nt][c] = 0.f;
#pragma unroll
        for (int kc = 0; kc < 4; kc++) {
            unsigned a0 = Qs[(kc * 8 + tig) * 72 + w * 16 + g];
            unsigned a1 = Qs[(kc * 8 + tig) * 72 + w * 16 + g + 8];
            unsigned a2 = Qs[(kc * 8 + tig + 4) * 72 + w * 16 + g];
            unsigned a3 = Qs[(kc * 8 + tig + 4) * 72 + w * 16 + g + 8];
#pragma unroll
            for (int nt = 0; nt < 8; nt++) {
                unsigned b0 = Ks[(kc * 8 + tig) * 72 + nt * 8 + g];
                unsigned b1 = Ks[(kc * 8 + tig + 4) * 72 + nt * 8 + g];
                mma8(sa[nt], a0, a1, a2, a3, b0, b1);
            }
        }
        // + pair bias
#pragma unroll
        for (int nt = 0; nt < 8; nt++) {
            float2 p0 = *(const float2*)(pb0 + jt + nt * 8 + 2 * tig);
            float2 p1 = *(const float2*)(pb1 + jt + nt * 8 + 2 * tig);
            sa[nt][0] += p0.x; sa[nt][1] += p0.y;
            sa[nt][2] += p1.x; sa[nt][3] += p1.y;
        }
        // online softmax (rows g, g+8); 4 lanes share a row
        float t0 = -1e30f, t1 = -1e30f;
#pragma unroll
        for (int nt = 0; nt < 8; nt++) {
            t0 = fmaxf(t0, fmaxf(sa[nt][0], sa[nt][1]));
            t1 = fmaxf(t1, fmaxf(sa[nt][2], sa[nt][3]));
        }
        t0 = fmaxf(t0, __shfl_xor_sync(0xffffffffu, t0, 1));
        t0 = fmaxf(t0, __shfl_xor_sync(0xffffffffu, t0, 2));
        t1 = fmaxf(t1, __shfl_xor_sync(0xffffffffu, t1, 1));
        t1 = fmaxf(t1, __shfl_xor_sync(0xffffffffu, t1, 2));
        float mn0 = fmaxf(mrow0, t0), mn1 = fmaxf(mrow1, t1);
        float corr0 = __expf(mrow0 - mn0), corr1 = __expf(mrow1 - mn1);
        mrow0 = mn0; mrow1 = mn1;
        float l0 = 0.f, l1 = 0.f;
        unsigned* ps0 = Ps + (w * 16 + g) * 68;
        unsigned* ps1 = Ps + (w * 16 + g + 8) * 68;
#pragma unroll
        for (int nt = 0; nt < 8; nt++) {
            float p00 = __expf(sa[nt][0] - mn0);
            float p01 = __expf(sa[nt][1] - mn0);
            float p10 = __expf(sa[nt][2] - mn1);
            float p11 = __expf(sa[nt][3] - mn1);
            l0 += p00 + p01; l1 += p10 + p11;
            ps0[nt * 8 + 2 * tig]     = f2tf(p00);
            ps0[nt * 8 + 2 * tig + 1] = f2tf(p01);
            ps1[nt * 8 + 2 * tig]     = f2tf(p10);
            ps1[nt * 8 + 2 * tig + 1] = f2tf(p11);
        }
        l0 += __shfl_xor_sync(0xffffffffu, l0, 1);
        l0 += __shfl_xor_sync(0xffffffffu, l0, 2);
        l1 += __shfl_xor_sync(0xffffffffu, l1, 1);
        l1 += __shfl_xor_sync(0xffffffffu, l1, 2);
        lsum0 = lsum0 * corr0 + l0;
        lsum1 = lsum1 * corr1 + l1;
#pragma unroll
        for (int nt = 0; nt < 4; nt++) {
            oacc[nt][0] *= corr0; oacc[nt][1] *= corr0;
            oacc[nt][2] *= corr1; oacc[nt][3] *= corr1;
        }
        __syncwarp();

        // O += P @ V   (A = P[i][j] from Ps, B = V[j][d] from Vs[d][j])
#pragma unroll
        for (int kc = 0; kc < 8; kc++) {
            unsigned a0 = Ps[(w * 16 + g) * 68 + kc * 8 + tig];
            unsigned a1 = Ps[(w * 16 + g + 8) * 68 + kc * 8 + tig];
            unsigned a2 = Ps[(w * 16 + g) * 68 + kc * 8 + tig + 4];
            unsigned a3 = Ps[(w * 16 + g + 8) * 68 + kc * 8 + tig + 4];
#pragma unroll
            for (int nt = 0; nt < 4; nt++) {
                unsigned b0 = Vs[(nt * 8 + g) * 72 + kc * 8 + tig];
                unsigned b1 = Vs[(nt * 8 + g) * 72 + kc * 8 + tig + 4];
                mma8(oacc[nt], a0, a1, a2, a3, b0, b1);
            }
        }
        __syncwarp();
    }

    // epilogue: normalize, gate, store to g_att[m][h*32+d]
    float inv0 = 1.f / lsum0, inv1 = 1.f / lsum1;
    int tg0 = i0 + w * 16 + g, tg1 = tg0 + 8;
#pragma unroll
    for (int nt = 0; nt < 4; nt++) {
        int d = nt * 8 + 2 * tig;
        const float* gq0 = g_qkvT + (size_t)(d * 32 + 24 + h) * MTOT + b * NT;
        const float* gq1 = g_qkvT + (size_t)((d + 1) * 32 + 24 + h) * MTOT + b * NT;
        float gv00 = gq0[tg0], gv01 = gq1[tg0];
        float gv10 = gq0[tg1], gv11 = gq1[tg1];
        float2 o0, o1;
        o0.x = oacc[nt][0] * inv0 * (1.f / (1.f + __expf(-gv00)));
        o0.y = oacc[nt][1] * inv0 * (1.f / (1.f + __expf(-gv01)));
        o1.x = oacc[nt][2] * inv1 * (1.f / (1.f + __expf(-gv10)));
        o1.y = oacc[nt][3] * inv1 * (1.f / (1.f + __expf(-gv11)));
        *(float2*)&g_att[((size_t)b * NT + tg0) * CM + h * 32 + d] = o0;
        *(float2*)&g_att[((size_t)b * NT + tg1) * CM + h * 32 + d] = o1;
    }
}

// ============================================================
// K4: out = g_att @ W0  (M=4096,K=256,N=256)
// ============================================================
__global__ void __launch_bounds__(256) out_kernel(const float* __restrict__ W0,
                                                  float* __restrict__ out) {
    __shared__ __align__(16) unsigned As[128 * 36];
    __shared__ __align__(16) unsigned Bs[32 * 72];
    const int tid = threadIdx.x;
    const int warp = tid >> 5, lane = tid & 31;
    const int g = lane >> 2, tig = lane & 3;
    const int wm = warp >> 1, wn = warp & 1;
    const int m0 = blockIdx.x * 128, n0 = blockIdx.y * 64;

    float acc[2][4][4];
#pragma unroll
    for (int i = 0; i < 2; i++)
#pragma unroll
        for (int j = 0; j < 4; j++)
#pragma unroll
            for (int c = 0; c < 4; c++) acc[i][j][c] = 0.f;

    for (int k0 = 0; k0 < CM; k0 += 32) {
        __syncthreads();
        {
            int row = tid >> 1, half = tid & 1;
            const float* src = g_att + (size_t)(m0 + row) * CM + k0 + half * 16;
            unsigned* dst = As + row * 36 + half * 16;
#pragma unroll
            for (int i = 0; i < 4; i++) {
                float4 v = *(const float4*)(src + i * 4);
                dst[i*4+0] = f2tf(v.x); dst[i*4+1] = f2tf(v.y);
                dst[i*4+2] = f2tf(v.z); dst[i*4+3] = f2tf(v.w);
            }
        }
        {
#pragma unroll
            for (int p = 0; p < 2; p++) {
                int row = (tid >> 4) + p * 16, c4 = (tid & 15) * 4;
                float4 v = *(const float4*)(W0 + (size_t)(k0 + row) * CM + n0 + c4);
                unsigned* dst = Bs + row * 72 + c4;
                dst[0] = f2tf(v.x); dst[1] = f2tf(v.y);
                dst[2] = f2tf(v.z); dst[3] = f2tf(v.w);
            }
        }
        __syncthreads();
#pragma unroll
        for (int kc = 0; kc < 4; kc++) {
            unsigned a[2][4];
#pragma unroll
            for (int mt = 0; mt < 2; mt++) {
                int r = wm * 32 + mt * 16;
                a[mt][0] = As[(r + g) * 36 + kc * 8 + tig];
                a[mt][1] = As[(r + g + 8) * 36 + kc * 8 + tig];
                a[mt][2] = As[(r + g) * 36 + kc * 8 + tig + 4];
                a[mt][3] = As[(r + g + 8) * 36 + kc * 8 + tig + 4];
            }
#pragma unroll
            for (int nt = 0; nt < 4; nt++) {
                int c = wn * 32 + nt * 8;
                unsigned b0 = Bs[(kc * 8 + tig) * 72 + c + g];
                unsigned b1 = Bs[(kc * 8 + tig + 4) * 72 + c + g];
                mma8(acc[0][nt], a[0][0], a[0][1], a[0][2], a[0][3], b0, b1);
                mma8(acc[1][nt], a[1][0], a[1][1], a[1][2], a[1][3], b0, b1);
            }
        }
    }
#pragma unroll
    for (int mt = 0; mt < 2; mt++) {
        int m = m0 + wm * 32 + mt * 16 + g;
#pragma unroll
        for (int nt = 0; nt < 4; nt++) {
            int n = n0 + wn * 32 + nt * 8 + 2 * tig;
            float2 o0 = make_float2(acc[mt][nt][0], acc[mt][nt][1]);
            float2 o1 = make_float2(acc[mt][nt][2], acc[mt][nt][3]);
            *(float2*)&out[(size_t)m * CM + n] = o0;
            *(float2*)&out[(size_t)(m + 8) * CM + n] = o1;
        }
    }
}

// ============================================================
extern "C" void kernel_launch(void* const* d_in, const int* in_sizes, int n_in,
                              void* d_out, int out_size) {
    (void)in_sizes; (void)n_in; (void)out_size;
    const float* x        = (const float*)d_in[0];
    const float* bias_rep = (const float*)d_in[1];
    const float* Wqkv     = (const float*)d_in[2];
    const float* W0       = (const float*)d_in[3];
    const float* Wb       = (const float*)d_in[4];
    const float* bb       = (const float*)d_in[5];
    float* out = (float*)d_out;

    qkv_kernel<<<dim3(32, 16), 256>>>(x, Wqkv);
    bias_kernel<<<dim3(1024, 16), 128>>>(bias_rep, Wb, bb);
    attn_kernel<<<dim3(32, 16), 128>>>();
    out_kernel<<<dim3(32, 4), 256>>>(W0, out);
}

// round 4
// speedup vs baseline: 2.9579x; 1.0244x over previous
#include <cuda_runtime.h>
#include <math.h>

#define NB 4
#define NT 1024
#define CM 256
#define NH 8
#define DHD 32
#define MTOT (NB*NT)   // 4096

// ---- scratch (device globals) ----
// [n=1024][m=4096], n = d*32 + kk*8 + h ; q/k/v hold tf32-bit floats (q pre-scaled), g fp32
__device__ float g_qkvT[(size_t)4*CM*MTOT];
__device__ float g_pb[(size_t)NH*NT*NT];      // [h][i*1024+j]  fp32
__device__ float g_att[(size_t)MTOT*CM];      // [m][h*32+d]    tf32-bit floats

__device__ __forceinline__ unsigned f2tf(float x) {
    unsigned r; asm("cvt.rna.tf32.f32 %0, %1;" : "=r"(r) : "f"(x)); return r;
}
__device__ __forceinline__ void mma8(float* d, unsigned a0, unsigned a1,
                                     unsigned a2, unsigned a3,
                                     unsigned b0, unsigned b1) {
    asm("mma.sync.aligned.m16n8k8.row.col.f32.tf32.tf32.f32 "
        "{%0,%1,%2,%3}, {%4,%5,%6,%7}, {%8,%9}, {%0,%1,%2,%3};"
        : "+f"(d[0]), "+f"(d[1]), "+f"(d[2]), "+f"(d[3])
        : "r"(a0), "r"(a1), "r"(a2), "r"(a3), "r"(b0), "r"(b1));
}

#define QKV_BLOCKS 512
#define FUSED_SMEM 67584   // bias role: 128*132*4

// ============================================================
// K1 fused: blocks [0,512) -> qkv GEMM ; blocks [512,8704) -> pair-bias GEMM
// ============================================================
__global__ void __launch_bounds__(256) fused1_kernel(const float* __restrict__ x,
                                                     const float* __restrict__ Wqkv,
                                                     const float* __restrict__ bias_rep,
                                                     const float* __restrict__ Wb,
                                                     const float* __restrict__ bb) {
    extern __shared__ __align__(16) unsigned char smem_raw[];
    const int tid = threadIdx.x;
    const int warp = tid >> 5, lane = tid & 31;
    const int g = lane >> 2, tig = lane & 3;

    if (blockIdx.x < QKV_BLOCKS) {
        // ---------------- qkv role: x @ Wqkv -> g_qkvT ----------------
        unsigned* As = (unsigned*)smem_raw;        // [128][36]
        unsigned* Bs = As + 128 * 36;              // [32][72]
        float* Ts = (float*)smem_raw;              // epilogue [64][132]
        const int wm = warp >> 1, wn = warp & 1;
        const int m0 = ((int)blockIdx.x & 31) * 128;
        const int n0 = ((int)blockIdx.x >> 5) * 64;

        float acc[2][4][4];
#pragma unroll
        for (int i = 0; i < 2; i++)
#pragma unroll
            for (int j = 0; j < 4; j++)
#pragma unroll
                for (int c = 0; c < 4; c++) acc[i][j][c] = 0.f;

        for (int k0 = 0; k0 < CM; k0 += 32) {
            __syncthreads();
            {   // stage A: 128 rows x 32 k
                int row = tid >> 1, half = tid & 1;
                const float* src = x + (size_t)(m0 + row) * CM + k0 + half * 16;
                unsigned* dst = As + row * 36 + half * 16;
#pragma unroll
                for (int i = 0; i < 4; i++) {
                    float4 v = *(const float4*)(src + i * 4);
                    dst[i*4+0] = f2tf(v.x); dst[i*4+1] = f2tf(v.y);
                    dst[i*4+2] = f2tf(v.z); dst[i*4+3] = f2tf(v.w);
                }
            }
            {   // stage B: 32 rows x 64 n
#pragma unroll
                for (int p = 0; p < 2; p++) {
                    int row = (tid >> 4) + p * 16, c4 = (tid & 15) * 4;
                    float4 v = *(const float4*)(Wqkv + (size_t)(k0 + row) * 1024 + n0 + c4);
                    unsigned* dst = Bs + row * 72 + c4;
                    dst[0] = f2tf(v.x); dst[1] = f2tf(v.y);
                    dst[2] = f2tf(v.z); dst[3] = f2tf(v.w);
                }
            }
            __syncthreads();
#pragma unroll
            for (int kc = 0; kc < 4; kc++) {
                unsigned a[2][4];
#pragma unroll
                for (int mt = 0; mt < 2; mt++) {
                    int r = wm * 32 + mt * 16;
                    a[mt][0] = As[(r + g) * 36 + kc * 8 + tig];
                    a[mt][1] = As[(r + g + 8) * 36 + kc * 8 + tig];
                    a[mt][2] = As[(r + g) * 36 + kc * 8 + tig + 4];
                    a[mt][3] = As[(r + g + 8) * 36 + kc * 8 + tig + 4];
                }
#pragma unroll
                for (int nt = 0; nt < 4; nt++) {
                    int c = wn * 32 + nt * 8;
                    unsigned b0 = Bs[(kc * 8 + tig) * 72 + c + g];
                    unsigned b1 = Bs[(kc * 8 + tig + 4) * 72 + c + g];
                    mma8(acc[0][nt], a[0][0], a[0][1], a[0][2], a[0][3], b0, b1);
                    mma8(acc[1][nt], a[1][0], a[1][1], a[1][2], a[1][3], b0, b1);
                }
            }
        }
        // epilogue: transpose via smem; q pre-scaled tf32, k/v tf32, g fp32
        __syncthreads();
#pragma unroll
        for (int mt = 0; mt < 2; mt++) {
            int r = wm * 32 + mt * 16 + g;
#pragma unroll
            for (int nt = 0; nt < 4; nt++) {
                int c = wn * 32 + nt * 8 + 2 * tig;
                Ts[c * 132 + r]           = acc[mt][nt][0];
                Ts[(c + 1) * 132 + r]     = acc[mt][nt][1];
                Ts[c * 132 + r + 8]       = acc[mt][nt][2];
                Ts[(c + 1) * 132 + r + 8] = acc[mt][nt][3];
            }
        }
        __syncthreads();
        {
            int col = tid >> 2, q = tid & 3;
            int n = n0 + col;
            int kk = (n & 31) >> 3;
            float* dst = g_qkvT + (size_t)n * MTOT + m0 + q * 32;
            const float* srcT = Ts + col * 132 + q * 32;
            if (kk == 3) {
#pragma unroll
                for (int i = 0; i < 8; i++)
                    *(float4*)(dst + i * 4) = *(const float4*)(srcT + i * 4);
            } else {
                float sc = (kk == 0) ? 0.17677669529663687f : 1.0f;
#pragma unroll
                for (int i = 0; i < 8; i++) {
                    float4 v = *(const float4*)(srcT + i * 4);
                    float4 o;
                    o.x = __uint_as_float(f2tf(v.x * sc));
                    o.y = __uint_as_float(f2tf(v.y * sc));
                    o.z = __uint_as_float(f2tf(v.z * sc));
                    o.w = __uint_as_float(f2tf(v.w * sc));
                    *(float4*)(dst + i * 4) = o;
                }
            }
        }
    } else {
        // ---------------- bias role: pb[h][i*1024+j] ----------------
        unsigned* As = (unsigned*)smem_raw;        // [128][132]
        const int bid = (int)blockIdx.x - QKV_BLOCKS;   // 0..8191
        const int bi = bid >> 3;                   // i
        const int j0 = (bid & 7) * 128;            // j tile
        const int w = warp;

        unsigned wb0[16], wb1[16];
#pragma unroll
        for (int kc = 0; kc < 16; kc++) {
            wb0[kc] = f2tf(__ldg(&Wb[(kc * 8 + tig) * 8 + g]));
            wb1[kc] = f2tf(__ldg(&Wb[(kc * 8 + tig + 4) * 8 + g]));
        }
        float bbv0 = __ldg(&bb[2 * tig]);
        float bbv1 = __ldg(&bb[2 * tig + 1]);

#pragma unroll
        for (int p = 0; p < 16; p++) {
            int idx = tid + p * 256;               // 0..4095 float4s
            int row = idx >> 5, c4 = (idx & 31) * 4;
            float4 v = *(const float4*)(bias_rep +
                        ((size_t)bi * NT + j0 + row) * 128 + c4);
            unsigned* dst = As + row * 132 + c4;
            dst[0] = f2tf(v.x); dst[1] = f2tf(v.y);
            dst[2] = f2tf(v.z); dst[3] = f2tf(v.w);
        }
        __syncthreads();

        float dd[4] = {0.f, 0.f, 0.f, 0.f};
#pragma unroll
        for (int kc = 0; kc < 16; kc++) {
            unsigned a0 = As[(w * 16 + g) * 132 + kc * 8 + tig];
            unsigned a1 = As[(w * 16 + g + 8) * 132 + kc * 8 + tig];
            unsigned a2 = As[(w * 16 + g) * 132 + kc * 8 + tig + 4];
            unsigned a3 = As[(w * 16 + g + 8) * 132 + kc * 8 + tig + 4];
            mma8(dd, a0, a1, a2, a3, wb0[kc], wb1[kc]);
        }
        size_t m = (size_t)bi * NT + j0 + w * 16 + g;
        g_pb[(size_t)(2 * tig) * (NT * NT)     + m]     = dd[0] + bbv0;
        g_pb[(size_t)(2 * tig + 1) * (NT * NT) + m]     = dd[1] + bbv1;
        g_pb[(size_t)(2 * tig) * (NT * NT)     + m + 8] = dd[2] + bbv0;
        g_pb[(size_t)(2 * tig + 1) * (NT * NT) + m + 8] = dd[3] + bbv1;
    }
}

// ============================================================
// K3: flash attention with pair bias + gate, tf32 HMMA
// 128 thr = 4 warps; block = (b,h) x 64 q-rows
// q/k/v arrive as tf32 bit-patterns (q pre-scaled) -> raw copies
// ============================================================
__global__ void __launch_bounds__(128) attn_kernel() {
    __shared__ __align__(16) unsigned Qs[32 * 72];   // [d][i]
    __shared__ __align__(16) unsigned Ks[32 * 72];   // [d][j]
    __shared__ __align__(16) unsigned Vs[32 * 72];   // [d][j]
    __shared__ __align__(16) unsigned Ps[64 * 68];   // [i][j] tf32

    const int bh = blockIdx.x;
    const int b = bh >> 3, h = bh & 7;
    const int i0 = blockIdx.y * 64;
    const int tid = threadIdx.x;
    const int w = tid >> 5, lane = tid & 31;
    const int g = lane >> 2, tig = lane & 3;

    // stage Q [d][i]  (raw tf32 bits, pre-scaled)
    {
        int d = w * 8 + (lane >> 2);
        int c0 = (lane & 3) * 16;
        const uint4* src = (const uint4*)(g_qkvT + (size_t)(d * 32 + h) * MTOT + b * NT + i0 + c0);
        uint4* dst = (uint4*)(Qs + d * 72 + c0);
#pragma unroll
        for (int i = 0; i < 4; i++) dst[i] = src[i];
    }

    float oacc[4][4];
#pragma unroll
    for (int i = 0; i < 4; i++)
#pragma unroll
        for (int c = 0; c < 4; c++) oacc[i][c] = 0.f;
    float mrow0 = -1e30f, mrow1 = -1e30f, lsum0 = 0.f, lsum1 = 0.f;

    const float* pb0 = g_pb + (size_t)h * (NT * NT) + (size_t)(i0 + w * 16 + g) * NT;
    const float* pb1 = pb0 + 8 * NT;

    for (int jt = 0; jt < NT; jt += 64) {
        __syncthreads();
        {   // stage K, V [d][j]  (raw)
            int d = w * 8 + (lane >> 2);
            int c0 = (lane & 3) * 16;
            const uint4* ks = (const uint4*)(g_qkvT + (size_t)(d * 32 + 8 + h) * MTOT + b * NT + jt + c0);
            const uint4* vs = (const uint4*)(g_qkvT + (size_t)(d * 32 + 16 + h) * MTOT + b * NT + jt + c0);
            uint4* kd = (uint4*)(Ks + d * 72 + c0);
            uint4* vd = (uint4*)(Vs + d * 72 + c0);
#pragma unroll
            for (int i = 0; i < 4; i++) { kd[i] = ks[i]; vd[i] = vs[i]; }
        }
        __syncthreads();

        // S = Q K^T  (8 n-tiles of 8 cols)
        float sa[8][4];
#pragma unroll
        for (int nt = 0; nt < 8; nt++)
#pragma unroll
            for (int c = 0; c < 4; c++) sa[nt][c] = 0.f;
#pragma unroll
        for (int kc = 0; kc < 4; kc++) {
            unsigned a0 = Qs[(kc * 8 + tig) * 72 + w * 16 + g];
            unsigned a1 = Qs[(kc * 8 + tig) * 72 + w * 16 + g + 8];
            unsigned a2 = Qs[(kc * 8 + tig + 4) * 72 + w * 16 + g];
            unsigned a3 = Qs[(kc * 8 + tig + 4) * 72 + w * 16 + g + 8];
#pragma unroll
            for (int nt = 0; nt < 8; nt++) {
                unsigned b0 = Ks[(kc * 8 + tig) * 72 + nt * 8 + g];
                unsigned b1 = Ks[(kc * 8 + tig + 4) * 72 + nt * 8 + g];
                mma8(sa[nt], a0, a1, a2, a3, b0, b1);
            }
        }
        // + pair bias
#pragma unroll
        for (int nt = 0; nt < 8; nt++) {
            float2 p0 = *(const float2*)(pb0 + jt + nt * 8 + 2 * tig);
            float2 p1 = *(const float2*)(pb1 + jt + nt * 8 + 2 * tig);
            sa[nt][0] += p0.x; sa[nt][1] += p0.y;
            sa[nt][2] += p1.x; sa[nt][3] += p1.y;
        }
        // online softmax (rows g, g+8); 4 lanes share a row
        float t0 = -1e30f, t1 = -1e30f;
#pragma unroll
        for (int nt = 0; nt < 8; nt++) {
            t0 = fmaxf(t0, fmaxf(sa[nt][0], sa[nt][1]));
            t1 = fmaxf(t1, fmaxf(sa[nt][2], sa[nt][3]));
        }
        t0 = fmaxf(t0, __shfl_xor_sync(0xffffffffu, t0, 1));
        t0 = fmaxf(t0, __shfl_xor_sync(0xffffffffu, t0, 2));
        t1 = fmaxf(t1, __shfl_xor_sync(0xffffffffu, t1, 1));
        t1 = fmaxf(t1, __shfl_xor_sync(0xffffffffu, t1, 2));
        float mn0 = fmaxf(mrow0, t0), mn1 = fmaxf(mrow1, t1);
        float corr0 = __expf(mrow0 - mn0), corr1 = __expf(mrow1 - mn1);
        mrow0 = mn0; mrow1 = mn1;
        float l0 = 0.f, l1 = 0.f;
        unsigned* ps0 = Ps + (w * 16 + g) * 68;
        unsigned* ps1 = Ps + (w * 16 + g + 8) * 68;
#pragma unroll
        for (int nt = 0; nt < 8; nt++) {
            float p00 = __expf(sa[nt][0] - mn0);
            float p01 = __expf(sa[nt][1] - mn0);
            float p10 = __expf(sa[nt][2] - mn1);
            float p11 = __expf(sa[nt][3] - mn1);
            l0 += p00 + p01; l1 += p10 + p11;
            ps0[nt * 8 + 2 * tig]     = f2tf(p00);
            ps0[nt * 8 + 2 * tig + 1] = f2tf(p01);
            ps1[nt * 8 + 2 * tig]     = f2tf(p10);
            ps1[nt * 8 + 2 * tig + 1] = f2tf(p11);
        }
        l0 += __shfl_xor_sync(0xffffffffu, l0, 1);
        l0 += __shfl_xor_sync(0xffffffffu, l0, 2);
        l1 += __shfl_xor_sync(0xffffffffu, l1, 1);
        l1 += __shfl_xor_sync(0xffffffffu, l1, 2);
        lsum0 = lsum0 * corr0 + l0;
        lsum1 = lsum1 * corr1 + l1;
#pragma unroll
        for (int nt = 0; nt < 4; nt++) {
            oacc[nt][0] *= corr0; oacc[nt][1] *= corr0;
            oacc[nt][2] *= corr1; oacc[nt][3] *= corr1;
        }
        __syncwarp();

        // O += P @ V
#pragma unroll
        for (int kc = 0; kc < 8; kc++) {
            unsigned a0 = Ps[(w * 16 + g) * 68 + kc * 8 + tig];
            unsigned a1 = Ps[(w * 16 + g + 8) * 68 + kc * 8 + tig];
            unsigned a2 = Ps[(w * 16 + g) * 68 + kc * 8 + tig + 4];
            unsigned a3 = Ps[(w * 16 + g + 8) * 68 + kc * 8 + tig + 4];
#pragma unroll
            for (int nt = 0; nt < 4; nt++) {
                unsigned b0 = Vs[(nt * 8 + g) * 72 + kc * 8 + tig];
                unsigned b1 = Vs[(nt * 8 + g) * 72 + kc * 8 + tig + 4];
                mma8(oacc[nt], a0, a1, a2, a3, b0, b1);
            }
        }
        __syncwarp();
    }

    // epilogue: normalize, gate (g fp32), store tf32 bits to g_att[m][h*32+d]
    float inv0 = 1.f / lsum0, inv1 = 1.f / lsum1;
    int tg0 = i0 + w * 16 + g, tg1 = tg0 + 8;
#pragma unroll
    for (int nt = 0; nt < 4; nt++) {
        int d = nt * 8 + 2 * tig;
        const float* gq0 = g_qkvT + (size_t)(d * 32 + 24 + h) * MTOT + b * NT;
        const float* gq1 = g_qkvT + (size_t)((d + 1) * 32 + 24 + h) * MTOT + b * NT;
        float gv00 = gq0[tg0], gv01 = gq1[tg0];
        float gv10 = gq0[tg1], gv11 = gq1[tg1];
        float2 o0, o1;
        o0.x = __uint_as_float(f2tf(oacc[nt][0] * inv0 * (1.f / (1.f + __expf(-gv00)))));
        o0.y = __uint_as_float(f2tf(oacc[nt][1] * inv0 * (1.f / (1.f + __expf(-gv01)))));
        o1.x = __uint_as_float(f2tf(oacc[nt][2] * inv1 * (1.f / (1.f + __expf(-gv10)))));
        o1.y = __uint_as_float(f2tf(oacc[nt][3] * inv1 * (1.f / (1.f + __expf(-gv11)))));
        *(float2*)&g_att[((size_t)b * NT + tg0) * CM + h * 32 + d] = o0;
        *(float2*)&g_att[((size_t)b * NT + tg1) * CM + h * 32 + d] = o1;
    }
}

// ============================================================
// K4: out = g_att @ W0  (M=4096,K=256,N=256), 64x64 tile, 256 blocks
// ============================================================
__global__ void __launch_bounds__(256) out_kernel(const float* __restrict__ W0,
                                                  float* __restrict__ out) {
    __shared__ __align__(16) unsigned As[64 * 36];
    __shared__ __align__(16) unsigned Bs[32 * 72];
    const int tid = threadIdx.x;
    const int warp = tid >> 5, lane = tid & 31;
    const int g = lane >> 2, tig = lane & 3;
    const int wm = warp >> 2, wn = warp & 3;
    const int m0 = blockIdx.x * 64, n0 = blockIdx.y * 64;

    float acc[2][2][4];
#pragma unroll
    for (int i = 0; i < 2; i++)
#pragma unroll
        for (int j = 0; j < 2; j++)
#pragma unroll
            for (int c = 0; c < 4; c++) acc[i][j][c] = 0.f;

    for (int k0 = 0; k0 < CM; k0 += 32) {
        __syncthreads();
        {   // A: raw tf32 bits, 64 rows x 32 k
#pragma unroll
            for (int p = 0; p < 2; p++) {
                int idx = tid + p * 256;
                int row = idx >> 3, c4 = (idx & 7) * 4;
                *(uint4*)(As + row * 36 + c4) =
                    *(const uint4*)(g_att + (size_t)(m0 + row) * CM + k0 + c4);
            }
        }
        {   // B: 32 rows x 64 n, cvt
#pragma unroll
            for (int p = 0; p < 2; p++) {
                int idx = tid + p * 256;
                int row = idx >> 4, c4 = (idx & 15) * 4;
                float4 v = *(const float4*)(W0 + (size_t)(k0 + row) * CM + n0 + c4);
                unsigned* dst = Bs + row * 72 + c4;
                dst[0] = f2tf(v.x); dst[1] = f2tf(v.y);
                dst[2] = f2tf(v.z); dst[3] = f2tf(v.w);
            }
        }
        __syncthreads();
#pragma unroll
        for (int kc = 0; kc < 4; kc++) {
            unsigned a[2][4];
#pragma unroll
            for (int mt = 0; mt < 2; mt++) {
                int r = wm * 32 + mt * 16;
                a[mt][0] = As[(r + g) * 36 + kc * 8 + tig];
                a[mt][1] = As[(r + g + 8) * 36 + kc * 8 + tig];
                a[mt][2] = As[(r + g) * 36 + kc * 8 + tig + 4];
                a[mt][3] = As[(r + g + 8) * 36 + kc * 8 + tig + 4];
            }
#pragma unroll
            for (int nt = 0; nt < 2; nt++) {
                int c = wn * 16 + nt * 8;
                unsigned b0 = Bs[(kc * 8 + tig) * 72 + c + g];
                unsigned b1 = Bs[(kc * 8 + tig + 4) * 72 + c + g];
                mma8(acc[0][nt], a[0][0], a[0][1], a[0][2], a[0][3], b0, b1);
                mma8(acc[1][nt], a[1][0], a[1][1], a[1][2], a[1][3], b0, b1);
            }
        }
    }
#pragma unroll
    for (int mt = 0; mt < 2; mt++) {
        int m = m0 + wm * 32 + mt * 16 + g;
#pragma unroll
        for (int nt = 0; nt < 2; nt++) {
            int n = n0 + wn * 16 + nt * 8 + 2 * tig;
            *(float2*)&out[(size_t)m * CM + n]       = make_float2(acc[mt][nt][0], acc[mt][nt][1]);
            *(float2*)&out[(size_t)(m + 8) * CM + n] = make_float2(acc[mt][nt][2], acc[mt][nt][3]);
        }
    }
}

// ============================================================
extern "C" void kernel_launch(void* const* d_in, const int* in_sizes, int n_in,
                              void* d_out, int out_size) {
    (void)in_sizes; (void)n_in; (void)out_size;
    const float* x        = (const float*)d_in[0];
    const float* bias_rep = (const float*)d_in[1];
    const float* Wqkv     = (const float*)d_in[2];
    const float* W0       = (const float*)d_in[3];
    const float* Wb       = (const float*)d_in[4];
    const float* bb       = (const float*)d_in[5];
    float* out = (float*)d_out;

    cudaFuncSetAttribute(fused1_kernel,
                         cudaFuncAttributeMaxDynamicSharedMemorySize, FUSED_SMEM);
    fused1_kernel<<<QKV_BLOCKS + 8192, 256, FUSED_SMEM>>>(x, Wqkv, bias_rep, Wb, bb);
    attn_kernel<<<dim3(32, 16), 128>>>();
    out_kernel<<<dim3(64, 4), 256>>>(W0, out);
}

// round 6
// speedup vs baseline: 3.7977x; 1.2839x over previous
#include <cuda_runtime.h>
#include <math.h>

#define NB 4
#define NT 1024
#define CM 256
#define NH 8
#define DHD 32
#define MTOT (NB*NT)   // 4096
#define NTSQ (NT*NT)

// q pre-scale: 32^-0.5 * log2(e)  (exp2-domain softmax)
#define QSCALE (0.17677669529663687f * 1.4426950408889634f)
#define LOG2E  1.4426950408889634f

// ---- scratch (device globals) ----
// [n=1024][m=4096], n = d*32 + kk*8 + h ; q tf32*QSCALE, k/v tf32 (RNA-rounded), g fp32
__device__ float g_qkvT[(size_t)4*CM*MTOT];
__device__ float g_pb[(size_t)NH*NT*NT];      // [h][i*1024+j], already * log2e
__device__ float g_att[(size_t)MTOT*CM];      // [m][h*32+d]    tf32-bit floats

__device__ __forceinline__ unsigned f2tf(float x) {
    unsigned r; asm("cvt.rna.tf32.f32 %0, %1;" : "=r"(r) : "f"(x)); return r;
}
__device__ __forceinline__ unsigned fu(float x) { return __float_as_uint(x); }
__device__ __forceinline__ float ex2(float x) {
    float r; asm("ex2.approx.ftz.f32 %0, %1;" : "=f"(r) : "f"(x)); return r;
}
__device__ __forceinline__ void mma8(float* d, unsigned a0, unsigned a1,
                                     unsigned a2, unsigned a3,
                                     unsigned b0, unsigned b1) {
    asm("mma.sync.aligned.m16n8k8.row.col.f32.tf32.tf32.f32 "
        "{%0,%1,%2,%3}, {%4,%5,%6,%7}, {%8,%9}, {%0,%1,%2,%3};"
        : "+f"(d[0]), "+f"(d[1]), "+f"(d[2]), "+f"(d[3])
        : "r"(a0), "r"(a1), "r"(a2), "r"(a3), "r"(b0), "r"(b1));
}
__device__ __forceinline__ void cpa16(void* dst, const void* src) {
    unsigned s = (unsigned)__cvta_generic_to_shared(dst);
    asm volatile("cp.async.cg.shared.global [%0], [%1], 16;" :: "r"(s), "l"(src));
}
#define CP_COMMIT asm volatile("cp.async.commit_group;")
#define CP_WAIT0  asm volatile("cp.async.wait_group 0;")

#define QKV_BLOCKS 512
#define FUSED_SMEM 67584   // bias role: 128*132*4
#define ATTN_SMEM  55296   // Qs 17408 + 2*Ks 18432 + 2*Vs 19456

// ============================================================
// K1 fused: blocks [0,512) -> qkv GEMM ; blocks [512,8704) -> pair-bias
// ============================================================
__global__ void __launch_bounds__(256) fused1_kernel(const float* __restrict__ x,
                                                     const float* __restrict__ Wqkv,
                                                     const float* __restrict__ bias_rep,
                                                     const float* __restrict__ Wb,
                                                     const float* __restrict__ bb) {
    extern __shared__ __align__(16) unsigned char smem_raw[];
    const int tid = threadIdx.x;
    const int warp = tid >> 5, lane = tid & 31;
    const int g = lane >> 2, tig = lane & 3;

    if (blockIdx.x < QKV_BLOCKS) {
        // ---------------- qkv role ----------------
        float* As = (float*)smem_raw;              // [128][36] raw fp32
        float* Bs = As + 128 * 36;                 // [32][72]  raw fp32
        float* Ts = (float*)smem_raw;              // epilogue [64][132]
        const int wm = warp >> 1, wn = warp & 1;
        const int m0 = ((int)blockIdx.x & 31) * 128;
        const int n0 = ((int)blockIdx.x >> 5) * 64;

        float acc[2][4][4];
#pragma unroll
        for (int i = 0; i < 2; i++)
#pragma unroll
            for (int j = 0; j < 4; j++)
#pragma unroll
                for (int c = 0; c < 4; c++) acc[i][j][c] = 0.f;

        for (int k0 = 0; k0 < CM; k0 += 32) {
            __syncthreads();
            {   // stage A raw: 128 rows x 32 k
                int row = tid >> 1, half = tid & 1;
#pragma unroll
                for (int q = 0; q < 4; q++)
                    cpa16(As + row * 36 + half * 16 + q * 4,
                          x + (size_t)(m0 + row) * CM + k0 + half * 16 + q * 4);
            }
            {   // stage B raw: 32 rows x 64 n
#pragma unroll
                for (int p = 0; p < 2; p++) {
                    int row = (tid >> 4) + p * 16, c4 = (tid & 15) * 4;
                    cpa16(Bs + row * 72 + c4,
                          Wqkv + (size_t)(k0 + row) * 1024 + n0 + c4);
                }
            }
            CP_COMMIT; CP_WAIT0;
            __syncthreads();
#pragma unroll
            for (int kc = 0; kc < 4; kc++) {
                unsigned a[2][4];
#pragma unroll
                for (int mt = 0; mt < 2; mt++) {
                    int r = wm * 32 + mt * 16;
                    a[mt][0] = f2tf(As[(r + g) * 36 + kc * 8 + tig]);
                    a[mt][1] = f2tf(As[(r + g + 8) * 36 + kc * 8 + tig]);
                    a[mt][2] = f2tf(As[(r + g) * 36 + kc * 8 + tig + 4]);
                    a[mt][3] = f2tf(As[(r + g + 8) * 36 + kc * 8 + tig + 4]);
                }
#pragma unroll
                for (int nt = 0; nt < 4; nt++) {
                    int c = wn * 32 + nt * 8;
                    unsigned b0 = f2tf(Bs[(kc * 8 + tig) * 72 + c + g]);
                    unsigned b1 = f2tf(Bs[(kc * 8 + tig + 4) * 72 + c + g]);
                    mma8(acc[0][nt], a[0][0], a[0][1], a[0][2], a[0][3], b0, b1);
                    mma8(acc[1][nt], a[1][0], a[1][1], a[1][2], a[1][3], b0, b1);
                }
            }
        }
        // epilogue: transpose via smem; q tf32*QSCALE, k/v tf32, g fp32
        __syncthreads();
#pragma unroll
        for (int mt = 0; mt < 2; mt++) {
            int r = wm * 32 + mt * 16 + g;
#pragma unroll
            for (int nt = 0; nt < 4; nt++) {
                int c = wn * 32 + nt * 8 + 2 * tig;
                Ts[c * 132 + r]           = acc[mt][nt][0];
                Ts[(c + 1) * 132 + r]     = acc[mt][nt][1];
                Ts[c * 132 + r + 8]       = acc[mt][nt][2];
                Ts[(c + 1) * 132 + r + 8] = acc[mt][nt][3];
            }
        }
        __syncthreads();
        {
            int col = tid >> 2, q = tid & 3;
            int n = n0 + col;
            int kk = (n & 31) >> 3;
            float* dst = g_qkvT + (size_t)n * MTOT + m0 + q * 32;
            const float* srcT = Ts + col * 132 + q * 32;
            if (kk == 3) {
#pragma unroll
                for (int i = 0; i < 8; i++)
                    *(float4*)(dst + i * 4) = *(const float4*)(srcT + i * 4);
            } else {
                float sc = (kk == 0) ? QSCALE : 1.0f;
#pragma unroll
                for (int i = 0; i < 8; i++) {
                    float4 v = *(const float4*)(srcT + i * 4);
                    float4 o;
                    o.x = __uint_as_float(f2tf(v.x * sc));
                    o.y = __uint_as_float(f2tf(v.y * sc));
                    o.z = __uint_as_float(f2tf(v.z * sc));
                    o.w = __uint_as_float(f2tf(v.w * sc));
                    *(float4*)(dst + i * 4) = o;
                }
            }
        }
    } else {
        // ---------------- bias role ----------------
        float* As = (float*)smem_raw;              // [128][132] raw fp32
        const int bid = (int)blockIdx.x - QKV_BLOCKS;   // 0..8191
        const int bi = bid >> 3;                   // i
        const int j0 = (bid & 7) * 128;            // j tile
        const int w = warp;

        unsigned wb0[16], wb1[16];
#pragma unroll
        for (int kc = 0; kc < 16; kc++) {
            wb0[kc] = f2tf(__ldg(&Wb[(kc * 8 + tig) * 8 + g]));
            wb1[kc] = f2tf(__ldg(&Wb[(kc * 8 + tig + 4) * 8 + g]));
        }
        float bbv0 = __ldg(&bb[2 * tig]);
        float bbv1 = __ldg(&bb[2 * tig + 1]);

        // stage 128 rows x 128 c via cp.async (raw fp32)
#pragma unroll
        for (int p = 0; p < 16; p++) {
            int idx = tid + p * 256;               // 0..4095 16B-chunks
            int row = idx >> 5, c4 = (idx & 31) * 4;
            cpa16(As + row * 132 + c4,
                  bias_rep + ((size_t)bi * NT + j0 + row) * 128 + c4);
        }
        CP_COMMIT; CP_WAIT0;
        __syncthreads();

        float dd[4] = {0.f, 0.f, 0.f, 0.f};
#pragma unroll
        for (int kc = 0; kc < 16; kc++) {
            unsigned a0 = f2tf(As[(w * 16 + g) * 132 + kc * 8 + tig]);
            unsigned a1 = f2tf(As[(w * 16 + g + 8) * 132 + kc * 8 + tig]);
            unsigned a2 = f2tf(As[(w * 16 + g) * 132 + kc * 8 + tig + 4]);
            unsigned a3 = f2tf(As[(w * 16 + g + 8) * 132 + kc * 8 + tig + 4]);
            mma8(dd, a0, a1, a2, a3, wb0[kc], wb1[kc]);
        }
        size_t m = (size_t)bi * NT + j0 + w * 16 + g;
        g_pb[(size_t)(2 * tig) * NTSQ     + m]     = (dd[0] + bbv0) * LOG2E;
        g_pb[(size_t)(2 * tig + 1) * NTSQ + m]     = (dd[1] + bbv1) * LOG2E;
        g_pb[(size_t)(2 * tig) * NTSQ     + m + 8] = (dd[2] + bbv0) * LOG2E;
        g_pb[(size_t)(2 * tig + 1) * NTSQ + m + 8] = (dd[3] + bbv1) * LOG2E;
    }
}

// ============================================================
// K3: flash attention, tf32 HMMA, exp2-domain softmax
// 256 thr = 8 warps; block = (b,h) x 128 q-rows; warp = 16 rows
// K/V double-buffered cp.async; P via register shuffles (no smem P)
// ============================================================
__global__ void __launch_bounds__(256, 3) attn_kernel() {
    extern __shared__ float asmem[];
    float* Qs = asmem;                       // [32][136]
    float* Ksb0 = asmem + 4352;              // [32][72]
    float* Ksb1 = asmem + 6656;
    float* Vsb0 = asmem + 8960;              // [32][76]
    float* Vsb1 = asmem + 11392;

    const int bh = blockIdx.x;
    const int b = bh >> 3, h = bh & 7;
    const int i0 = blockIdx.y * 128;
    const int tid = threadIdx.x;
    const int w = tid >> 5, lane = tid & 31;
    const int g = lane >> 2, tig = lane & 3;

    // stage Q (once): [d][i] raw tf32 bits (pre-scaled incl log2e)
#pragma unroll
    for (int r = 0; r < 4; r++) {
        int c = tid + r * 256;
        int d = c >> 5, c4 = (c & 31) * 4;
        cpa16(Qs + d * 136 + c4,
              g_qkvT + (size_t)(d * 32 + h) * MTOT + b * NT + i0 + c4);
    }
    // stage K/V tile 0
#pragma unroll
    for (int r = 0; r < 2; r++) {
        int c = tid + r * 256;
        int d = c >> 4, c4 = (c & 15) * 4;
        cpa16(Ksb0 + d * 72 + c4, g_qkvT + (size_t)(d * 32 + 8 + h) * MTOT + b * NT + c4);
        cpa16(Vsb0 + d * 76 + c4, g_qkvT + (size_t)(d * 32 + 16 + h) * MTOT + b * NT + c4);
    }
    CP_COMMIT;

    float oacc[4][4];
#pragma unroll
    for (int i = 0; i < 4; i++)
#pragma unroll
        for (int c = 0; c < 4; c++) oacc[i][c] = 0.f;
    float mrow0 = -1e30f, mrow1 = -1e30f, lsum0 = 0.f, lsum1 = 0.f;

    const float* pb0 = g_pb + (size_t)h * NTSQ + (size_t)(i0 + w * 16 + g) * NT;
    const float* pb1 = pb0 + 8 * NT;

    for (int n = 0; n < 16; n++) {
        CP_WAIT0;
        __syncthreads();
        const float* Ks = (n & 1) ? Ksb1 : Ksb0;
        const float* Vs = (n & 1) ? Vsb1 : Vsb0;
        if (n < 15) {   // prefetch next tile into other buffer
            float* Kd = (n & 1) ? Ksb0 : Ksb1;
            float* Vd = (n & 1) ? Vsb0 : Vsb1;
            int jn = (n + 1) * 64;
#pragma unroll
            for (int r = 0; r < 2; r++) {
                int c = tid + r * 256;
                int d = c >> 4, c4 = (c & 15) * 4;
                cpa16(Kd + d * 72 + c4,
                      g_qkvT + (size_t)(d * 32 + 8 + h) * MTOT + b * NT + jn + c4);
                cpa16(Vd + d * 76 + c4,
                      g_qkvT + (size_t)(d * 32 + 16 + h) * MTOT + b * NT + jn + c4);
            }
            CP_COMMIT;
        }
        const int jt = n * 64;

        // S = Q K^T   (operands are pre-rounded tf32 bit patterns)
        float sa[8][4];
#pragma unroll
        for (int nt = 0; nt < 8; nt++)
#pragma unroll
            for (int c = 0; c < 4; c++) sa[nt][c] = 0.f;
#pragma unroll
        for (int kc = 0; kc < 4; kc++) {
            const float* qrow = Qs + (kc * 8 + tig) * 136 + w * 16 + g;
            unsigned a0 = fu(qrow[0]);
            unsigned a1 = fu(qrow[8]);
            unsigned a2 = fu(qrow[544]);
            unsigned a3 = fu(qrow[552]);
#pragma unroll
            for (int nt = 0; nt < 8; nt++) {
                unsigned b0 = fu(Ks[(kc * 8 + tig) * 72 + nt * 8 + g]);
                unsigned b1 = fu(Ks[(kc * 8 + tig + 4) * 72 + nt * 8 + g]);
                mma8(sa[nt], a0, a1, a2, a3, b0, b1);
            }
        }
        // + pair bias (already * log2e)
#pragma unroll
        for (int nt = 0; nt < 8; nt++) {
            float2 p0 = *(const float2*)(pb0 + jt + nt * 8 + 2 * tig);
            float2 p1 = *(const float2*)(pb1 + jt + nt * 8 + 2 * tig);
            sa[nt][0] += p0.x; sa[nt][1] += p0.y;
            sa[nt][2] += p1.x; sa[nt][3] += p1.y;
        }
        // online softmax in exp2 domain
        float t0 = -1e30f, t1 = -1e30f;
#pragma unroll
        for (int nt = 0; nt < 8; nt++) {
            t0 = fmaxf(t0, fmaxf(sa[nt][0], sa[nt][1]));
            t1 = fmaxf(t1, fmaxf(sa[nt][2], sa[nt][3]));
        }
        t0 = fmaxf(t0, __shfl_xor_sync(0xffffffffu, t0, 1));
        t0 = fmaxf(t0, __shfl_xor_sync(0xffffffffu, t0, 2));
        t1 = fmaxf(t1, __shfl_xor_sync(0xffffffffu, t1, 1));
        t1 = fmaxf(t1, __shfl_xor_sync(0xffffffffu, t1, 2));
        float mn0 = fmaxf(mrow0, t0), mn1 = fmaxf(mrow1, t1);
        float corr0 = ex2(mrow0 - mn0), corr1 = ex2(mrow1 - mn1);
        mrow0 = mn0; mrow1 = mn1;
        float l0 = 0.f, l1 = 0.f;
#pragma unroll
        for (int nt = 0; nt < 8; nt++) {
            sa[nt][0] = ex2(sa[nt][0] - mn0); l0 += sa[nt][0];
            sa[nt][1] = ex2(sa[nt][1] - mn0); l0 += sa[nt][1];
            sa[nt][2] = ex2(sa[nt][2] - mn1); l1 += sa[nt][2];
            sa[nt][3] = ex2(sa[nt][3] - mn1); l1 += sa[nt][3];
        }
        l0 += __shfl_xor_sync(0xffffffffu, l0, 1);
        l0 += __shfl_xor_sync(0xffffffffu, l0, 2);
        l1 += __shfl_xor_sync(0xffffffffu, l1, 1);
        l1 += __shfl_xor_sync(0xffffffffu, l1, 2);
        lsum0 = lsum0 * corr0 + l0;
        lsum1 = lsum1 * corr1 + l1;
#pragma unroll
        for (int nt = 0; nt < 4; nt++) {
            oacc[nt][0] *= corr0; oacc[nt][1] *= corr0;
            oacc[nt][2] *= corr1; oacc[nt][3] *= corr1;
        }

        // O += P @ V ; P A-frags via shuffles, RNA-rounded to tf32
        const int sl = g * 4 + (tig >> 1);
        const bool odd = tig & 1;
#pragma unroll
        for (int kc = 0; kc < 8; kc++) {
            float p0 = sa[kc][0], p1 = sa[kc][1], p2 = sa[kc][2], p3 = sa[kc][3];
            float u0 = __shfl_sync(0xffffffffu, p0, sl);
            float u1 = __shfl_sync(0xffffffffu, p1, sl);
            float u2 = __shfl_sync(0xffffffffu, p2, sl);
            float u3 = __shfl_sync(0xffffffffu, p3, sl);
            float v0 = __shfl_sync(0xffffffffu, p0, sl + 2);
            float v1 = __shfl_sync(0xffffffffu, p1, sl + 2);
            float v2 = __shfl_sync(0xffffffffu, p2, sl + 2);
            float v3 = __shfl_sync(0xffffffffu, p3, sl + 2);
            unsigned a0 = f2tf(odd ? u1 : u0);
            unsigned a1 = f2tf(odd ? u3 : u2);
            unsigned a2 = f2tf(odd ? v1 : v0);
            unsigned a3 = f2tf(odd ? v3 : v2);
#pragma unroll
            for (int nt = 0; nt < 4; nt++) {
                unsigned b0 = fu(Vs[(nt * 8 + g) * 76 + kc * 8 + tig]);
                unsigned b1 = fu(Vs[(nt * 8 + g) * 76 + kc * 8 + tig + 4]);
                mma8(oacc[nt], a0, a1, a2, a3, b0, b1);
            }
        }
    }

    // epilogue: normalize, gate (g fp32), store tf32 bits to g_att[m][h*32+d]
    float inv0 = 1.f / lsum0, inv1 = 1.f / lsum1;
    int tg0 = i0 + w * 16 + g, tg1 = tg0 + 8;
#pragma unroll
    for (int nt = 0; nt < 4; nt++) {
        int d = nt * 8 + 2 * tig;
        const float* gq0 = g_qkvT + (size_t)(d * 32 + 24 + h) * MTOT + b * NT;
        const float* gq1 = g_qkvT + (size_t)((d + 1) * 32 + 24 + h) * MTOT + b * NT;
        float gv00 = gq0[tg0], gv01 = gq1[tg0];
        float gv10 = gq0[tg1], gv11 = gq1[tg1];
        float2 o0, o1;
        o0.x = __uint_as_float(f2tf(oacc[nt][0] * inv0 * (1.f / (1.f + __expf(-gv00)))));
        o0.y = __uint_as_float(f2tf(oacc[nt][1] * inv0 * (1.f / (1.f + __expf(-gv01)))));
        o1.x = __uint_as_float(f2tf(oacc[nt][2] * inv1 * (1.f / (1.f + __expf(-gv10)))));
        o1.y = __uint_as_float(f2tf(oacc[nt][3] * inv1 * (1.f / (1.f + __expf(-gv11)))));
        *(float2*)&g_att[((size_t)b * NT + tg0) * CM + h * 32 + d] = o0;
        *(float2*)&g_att[((size_t)b * NT + tg1) * CM + h * 32 + d] = o1;
    }
}

// ============================================================
// K4: out = g_att @ W0  (M=4096,K=256,N=256), 64x64 tile
// ============================================================
__global__ void __launch_bounds__(256) out_kernel(const float* __restrict__ W0,
                                                  float* __restrict__ out) {
    __shared__ __align__(16) unsigned As[64 * 36];
    __shared__ __align__(16) unsigned Bs[32 * 72];
    const int tid = threadIdx.x;
    const int warp = tid >> 5, lane = tid & 31;
    const int g = lane >> 2, tig = lane & 3;
    const int wm = warp >> 2, wn = warp & 3;
    const int m0 = blockIdx.x * 64, n0 = blockIdx.y * 64;

    float acc[2][2][4];
#pragma unroll
    for (int i = 0; i < 2; i++)
#pragma unroll
        for (int j = 0; j < 2; j++)
#pragma unroll
            for (int c = 0; c < 4; c++) acc[i][j][c] = 0.f;

    for (int k0 = 0; k0 < CM; k0 += 32) {
        __syncthreads();
        {   // A: raw tf32 bits (g_att pre-rounded)
#pragma unroll
            for (int p = 0; p < 2; p++) {
                int idx = tid + p * 256;
                int row = idx >> 3, c4 = (idx & 7) * 4;
                *(uint4*)(As + row * 36 + c4) =
                    *(const uint4*)(g_att + (size_t)(m0 + row) * CM + k0 + c4);
            }
        }
        {   // B: W0, RNA-rounded to tf32
#pragma unroll
            for (int p = 0; p < 2; p++) {
                int idx = tid + p * 256;
                int row = idx >> 4, c4 = (idx & 15) * 4;
                float4 v = *(const float4*)(W0 + (size_t)(k0 + row) * CM + n0 + c4);
                unsigned* dst = Bs + row * 72 + c4;
                dst[0] = f2tf(v.x); dst[1] = f2tf(v.y);
                dst[2] = f2tf(v.z); dst[3] = f2tf(v.w);
            }
        }
        __syncthreads();
#pragma unroll
        for (int kc = 0; kc < 4; kc++) {
            unsigned a[2][4];
#pragma unroll
            for (int mt = 0; mt < 2; mt++) {
                int r = wm * 32 + mt * 16;
                a[mt][0] = As[(r + g) * 36 + kc * 8 + tig];
                a[mt][1] = As[(r + g + 8) * 36 + kc * 8 + tig];
                a[mt][2] = As[(r + g) * 36 + kc * 8 + tig + 4];
                a[mt][3] = As[(r + g + 8) * 36 + kc * 8 + tig + 4];
            }
#pragma unroll
            for (int nt = 0; nt < 2; nt++) {
                int c = wn * 16 + nt * 8;
                unsigned b0 = Bs[(kc * 8 + tig) * 72 + c + g];
                unsigned b1 = Bs[(kc * 8 + tig + 4) * 72 + c + g];
                mma8(acc[0][nt], a[0][0], a[0][1], a[0][2], a[0][3], b0, b1);
                mma8(acc[1][nt], a[1][0], a[1][1], a[1][2], a[1][3], b0, b1);
            }
        }
    }
#pragma unroll
    for (int mt = 0; mt < 2; mt++) {
        int m = m0 + wm * 32 + mt * 16 + g;
#pragma unroll
        for (int nt = 0; nt < 2; nt++) {
            int n = n0 + wn * 16 + nt * 8 + 2 * tig;
            *(float2*)&out[(size_t)m * CM + n]       = make_float2(acc[mt][nt][0], acc[mt][nt][1]);
            *(float2*)&out[(size_t)(m + 8) * CM + n] = make_float2(acc[mt][nt][2], acc[mt][nt][3]);
        }
    }
}

// ============================================================
extern "C" void kernel_launch(void* const* d_in, const int* in_sizes, int n_in,
                              void* d_out, int out_size) {
    (void)in_sizes; (void)n_in; (void)out_size;
    const float* x        = (const float*)d_in[0];
    const float* bias_rep = (const float*)d_in[1];
    const float* Wqkv     = (const float*)d_in[2];
    const float* W0       = (const float*)d_in[3];
    const float* Wb       = (const float*)d_in[4];
    const float* bb       = (const float*)d_in[5];
    float* out = (float*)d_out;

    cudaFuncSetAttribute(fused1_kernel,
                         cudaFuncAttributeMaxDynamicSharedMemorySize, FUSED_SMEM);
    cudaFuncSetAttribute(attn_kernel,
                         cudaFuncAttributeMaxDynamicSharedMemorySize, ATTN_SMEM);
    fused1_kernel<<<QKV_BLOCKS + 8192, 256, FUSED_SMEM>>>(x, Wqkv, bias_rep, Wb, bb);
    attn_kernel<<<dim3(32, 8), 256, ATTN_SMEM>>>();
    out_kernel<<<dim3(64, 4), 256>>>(W0, out);
}

// round 7
// speedup vs baseline: 3.9530x; 1.0409x over previous
#include <cuda_runtime.h>
#include <cuda_fp16.h>
#include <math.h>

#define NB 4
#define NT 1024
#define CM 256
#define NH 8
#define DHD 32
#define MTOT (NB*NT)   // 4096
#define NTSQ (NT*NT)

// q pre-scale: 32^-0.5 * log2(e)  (exp2-domain softmax)
#define QSCALE (0.17677669529663687f * 1.4426950408889634f)
#define LOG2E  1.4426950408889634f

// ---- scratch (device globals) ----
// [n=1024][m=4096], n = d*32 + kk*8 + h ; q tf32*QSCALE, k/v tf32 (RNA-rounded), g fp32
__device__ float g_qkvT[(size_t)4*CM*MTOT];
__device__ __half g_pbh[(size_t)NH*NT*NT];    // [h][i*1024+j], * log2e, fp16 (16 MB)
__device__ float g_att[(size_t)MTOT*CM];      // [m][h*32+d]    tf32-bit floats

__device__ __forceinline__ unsigned f2tf(float x) {
    unsigned r; asm("cvt.rna.tf32.f32 %0, %1;" : "=r"(r) : "f"(x)); return r;
}
__device__ __forceinline__ unsigned fu(float x) { return __float_as_uint(x); }
__device__ __forceinline__ float ex2(float x) {
    float r; asm("ex2.approx.ftz.f32 %0, %1;" : "=f"(r) : "f"(x)); return r;
}
__device__ __forceinline__ void mma8(float* d, unsigned a0, unsigned a1,
                                     unsigned a2, unsigned a3,
                                     unsigned b0, unsigned b1) {
    asm("mma.sync.aligned.m16n8k8.row.col.f32.tf32.tf32.f32 "
        "{%0,%1,%2,%3}, {%4,%5,%6,%7}, {%8,%9}, {%0,%1,%2,%3};"
        : "+f"(d[0]), "+f"(d[1]), "+f"(d[2]), "+f"(d[3])
        : "r"(a0), "r"(a1), "r"(a2), "r"(a3), "r"(b0), "r"(b1));
}
__device__ __forceinline__ void cpa16(void* dst, const void* src) {
    unsigned s = (unsigned)__cvta_generic_to_shared(dst);
    asm volatile("cp.async.cg.shared.global [%0], [%1], 16;" :: "r"(s), "l"(src));
}
#define CP_COMMIT asm volatile("cp.async.commit_group;")
#define CP_WAIT0  asm volatile("cp.async.wait_group 0;")

#define QKV_BLOCKS 512
#define FUSED_SMEM 67584   // bias role: 128*132*4
#define ATTN_SMEM  55296   // Qs 17408 + 2*Ks 18432 + 2*Vs 19456

// ============================================================
// K1 fused: blocks [0,512) -> qkv GEMM ; blocks [512,8704) -> pair-bias
// ============================================================
__global__ void __launch_bounds__(256) fused1_kernel(const float* __restrict__ x,
                                                     const float* __restrict__ Wqkv,
                                                     const float* __restrict__ bias_rep,
                                                     const float* __restrict__ Wb,
                                                     const float* __restrict__ bb) {
    extern __shared__ __align__(16) unsigned char smem_raw[];
    const int tid = threadIdx.x;
    const int warp = tid >> 5, lane = tid & 31;
    const int g = lane >> 2, tig = lane & 3;

    if (blockIdx.x < QKV_BLOCKS) {
        // ---------------- qkv role ----------------
        float* As = (float*)smem_raw;              // [128][36] raw fp32
        float* Bs = As + 128 * 36;                 // [32][72]  raw fp32
        float* Ts = (float*)smem_raw;              // epilogue [64][132]
        const int wm = warp >> 1, wn = warp & 1;
        const int m0 = ((int)blockIdx.x & 31) * 128;
        const int n0 = ((int)blockIdx.x >> 5) * 64;

        float acc[2][4][4];
#pragma unroll
        for (int i = 0; i < 2; i++)
#pragma unroll
            for (int j = 0; j < 4; j++)
#pragma unroll
                for (int c = 0; c < 4; c++) acc[i][j][c] = 0.f;

        for (int k0 = 0; k0 < CM; k0 += 32) {
            __syncthreads();
            {   // stage A raw: 128 rows x 32 k
                int row = tid >> 1, half = tid & 1;
#pragma unroll
                for (int q = 0; q < 4; q++)
                    cpa16(As + row * 36 + half * 16 + q * 4,
                          x + (size_t)(m0 + row) * CM + k0 + half * 16 + q * 4);
            }
            {   // stage B raw: 32 rows x 64 n
#pragma unroll
                for (int p = 0; p < 2; p++) {
                    int row = (tid >> 4) + p * 16, c4 = (tid & 15) * 4;
                    cpa16(Bs + row * 72 + c4,
                          Wqkv + (size_t)(k0 + row) * 1024 + n0 + c4);
                }
            }
            CP_COMMIT; CP_WAIT0;
            __syncthreads();
#pragma unroll
            for (int kc = 0; kc < 4; kc++) {
                unsigned a[2][4];
#pragma unroll
                for (int mt = 0; mt < 2; mt++) {
                    int r = wm * 32 + mt * 16;
                    a[mt][0] = f2tf(As[(r + g) * 36 + kc * 8 + tig]);
                    a[mt][1] = f2tf(As[(r + g + 8) * 36 + kc * 8 + tig]);
                    a[mt][2] = f2tf(As[(r + g) * 36 + kc * 8 + tig + 4]);
                    a[mt][3] = f2tf(As[(r + g + 8) * 36 + kc * 8 + tig + 4]);
                }
#pragma unroll
                for (int nt = 0; nt < 4; nt++) {
                    int c = wn * 32 + nt * 8;
                    unsigned b0 = f2tf(Bs[(kc * 8 + tig) * 72 + c + g]);
                    unsigned b1 = f2tf(Bs[(kc * 8 + tig + 4) * 72 + c + g]);
                    mma8(acc[0][nt], a[0][0], a[0][1], a[0][2], a[0][3], b0, b1);
                    mma8(acc[1][nt], a[1][0], a[1][1], a[1][2], a[1][3], b0, b1);
                }
            }
        }
        // epilogue: transpose via smem; q tf32*QSCALE, k/v tf32, g fp32
        __syncthreads();
#pragma unroll
        for (int mt = 0; mt < 2; mt++) {
            int r = wm * 32 + mt * 16 + g;
#pragma unroll
            for (int nt = 0; nt < 4; nt++) {
                int c = wn * 32 + nt * 8 + 2 * tig;
                Ts[c * 132 + r]           = acc[mt][nt][0];
                Ts[(c + 1) * 132 + r]     = acc[mt][nt][1];
                Ts[c * 132 + r + 8]       = acc[mt][nt][2];
                Ts[(c + 1) * 132 + r + 8] = acc[mt][nt][3];
            }
        }
        __syncthreads();
        {
            int col = tid >> 2, q = tid & 3;
            int n = n0 + col;
            int kk = (n & 31) >> 3;
            float* dst = g_qkvT + (size_t)n * MTOT + m0 + q * 32;
            const float* srcT = Ts + col * 132 + q * 32;
            if (kk == 3) {
#pragma unroll
                for (int i = 0; i < 8; i++)
                    *(float4*)(dst + i * 4) = *(const float4*)(srcT + i * 4);
            } else {
                float sc = (kk == 0) ? QSCALE : 1.0f;
#pragma unroll
                for (int i = 0; i < 8; i++) {
                    float4 v = *(const float4*)(srcT + i * 4);
                    float4 o;
                    o.x = __uint_as_float(f2tf(v.x * sc));
                    o.y = __uint_as_float(f2tf(v.y * sc));
                    o.z = __uint_as_float(f2tf(v.z * sc));
                    o.w = __uint_as_float(f2tf(v.w * sc));
                    *(float4*)(dst + i * 4) = o;
                }
            }
        }
    } else {
        // ---------------- bias role ----------------
        float* As = (float*)smem_raw;              // [128][132] raw fp32
        const int bid = (int)blockIdx.x - QKV_BLOCKS;   // 0..8191
        const int bi = bid >> 3;                   // i
        const int j0 = (bid & 7) * 128;            // j tile
        const int w = warp;

        unsigned wb0[16], wb1[16];
#pragma unroll
        for (int kc = 0; kc < 16; kc++) {
            wb0[kc] = f2tf(__ldg(&Wb[(kc * 8 + tig) * 8 + g]));
            wb1[kc] = f2tf(__ldg(&Wb[(kc * 8 + tig + 4) * 8 + g]));
        }
        float bbv0 = __ldg(&bb[2 * tig]);
        float bbv1 = __ldg(&bb[2 * tig + 1]);

        // stage 128 rows x 128 c via cp.async (raw fp32)
#pragma unroll
        for (int p = 0; p < 16; p++) {
            int idx = tid + p * 256;               // 0..4095 16B-chunks
            int row = idx >> 5, c4 = (idx & 31) * 4;
            cpa16(As + row * 132 + c4,
                  bias_rep + ((size_t)bi * NT + j0 + row) * 128 + c4);
        }
        CP_COMMIT; CP_WAIT0;
        __syncthreads();

        float dd[4] = {0.f, 0.f, 0.f, 0.f};
#pragma unroll
        for (int kc = 0; kc < 16; kc++) {
            unsigned a0 = f2tf(As[(w * 16 + g) * 132 + kc * 8 + tig]);
            unsigned a1 = f2tf(As[(w * 16 + g + 8) * 132 + kc * 8 + tig]);
            unsigned a2 = f2tf(As[(w * 16 + g) * 132 + kc * 8 + tig + 4]);
            unsigned a3 = f2tf(As[(w * 16 + g + 8) * 132 + kc * 8 + tig + 4]);
            mma8(dd, a0, a1, a2, a3, wb0[kc], wb1[kc]);
        }
        size_t m = (size_t)bi * NT + j0 + w * 16 + g;
        g_pbh[(size_t)(2 * tig) * NTSQ     + m]     = __float2half((dd[0] + bbv0) * LOG2E);
        g_pbh[(size_t)(2 * tig + 1) * NTSQ + m]     = __float2half((dd[1] + bbv1) * LOG2E);
        g_pbh[(size_t)(2 * tig) * NTSQ     + m + 8] = __float2half((dd[2] + bbv0) * LOG2E);
        g_pbh[(size_t)(2 * tig + 1) * NTSQ + m + 8] = __float2half((dd[3] + bbv1) * LOG2E);
    }
}

// ============================================================
// K3: flash attention, tf32 HMMA, exp2-domain softmax, fp16 pb
// 256 thr = 8 warps; block = (b,h) x 128 q-rows; warp = 16 rows
// K/V double-buffered cp.async; P via register shuffles (no smem P)
// ============================================================
__global__ void __launch_bounds__(256, 3) attn_kernel() {
    extern __shared__ float asmem[];
    float* Qs = asmem;                       // [32][136]
    float* Ksb0 = asmem + 4352;              // [32][72]
    float* Ksb1 = asmem + 6656;
    float* Vsb0 = asmem + 8960;              // [32][76]
    float* Vsb1 = asmem + 11392;

    const int bh = blockIdx.x;
    const int b = bh >> 3, h = bh & 7;
    const int i0 = blockIdx.y * 128;
    const int tid = threadIdx.x;
    const int w = tid >> 5, lane = tid & 31;
    const int g = lane >> 2, tig = lane & 3;

    // stage Q (once): [d][i] raw tf32 bits (pre-scaled incl log2e)
#pragma unroll
    for (int r = 0; r < 4; r++) {
        int c = tid + r * 256;
        int d = c >> 5, c4 = (c & 31) * 4;
        cpa16(Qs + d * 136 + c4,
              g_qkvT + (size_t)(d * 32 + h) * MTOT + b * NT + i0 + c4);
    }
    // stage K/V tile 0
#pragma unroll
    for (int r = 0; r < 2; r++) {
        int c = tid + r * 256;
        int d = c >> 4, c4 = (c & 15) * 4;
        cpa16(Ksb0 + d * 72 + c4, g_qkvT + (size_t)(d * 32 + 8 + h) * MTOT + b * NT + c4);
        cpa16(Vsb0 + d * 76 + c4, g_qkvT + (size_t)(d * 32 + 16 + h) * MTOT + b * NT + c4);
    }
    CP_COMMIT;

    float oacc[4][4];
#pragma unroll
    for (int i = 0; i < 4; i++)
#pragma unroll
        for (int c = 0; c < 4; c++) oacc[i][c] = 0.f;
    float mrow0 = -1e30f, mrow1 = -1e30f, lsum0 = 0.f, lsum1 = 0.f;

    const __half* pb0 = g_pbh + (size_t)h * NTSQ + (size_t)(i0 + w * 16 + g) * NT;
    const __half* pb1 = pb0 + 8 * NT;

    for (int n = 0; n < 16; n++) {
        CP_WAIT0;
        __syncthreads();
        const float* Ks = (n & 1) ? Ksb1 : Ksb0;
        const float* Vs = (n & 1) ? Vsb1 : Vsb0;
        if (n < 15) {   // prefetch next tile into other buffer
            float* Kd = (n & 1) ? Ksb0 : Ksb1;
            float* Vd = (n & 1) ? Vsb0 : Vsb1;
            int jn = (n + 1) * 64;
#pragma unroll
            for (int r = 0; r < 2; r++) {
                int c = tid + r * 256;
                int d = c >> 4, c4 = (c & 15) * 4;
                cpa16(Kd + d * 72 + c4,
                      g_qkvT + (size_t)(d * 32 + 8 + h) * MTOT + b * NT + jn + c4);
                cpa16(Vd + d * 76 + c4,
                      g_qkvT + (size_t)(d * 32 + 16 + h) * MTOT + b * NT + jn + c4);
            }
            CP_COMMIT;
        }
        const int jt = n * 64;

        // prefetch pair bias (fp16) into registers — overlaps with S MMAs
        __half2 hp0[8], hp1[8];
#pragma unroll
        for (int nt = 0; nt < 8; nt++) {
            hp0[nt] = *(const __half2*)(pb0 + jt + nt * 8 + 2 * tig);
            hp1[nt] = *(const __half2*)(pb1 + jt + nt * 8 + 2 * tig);
        }

        // S = Q K^T   (operands are pre-rounded tf32 bit patterns)
        float sa[8][4];
#pragma unroll
        for (int nt = 0; nt < 8; nt++)
#pragma unroll
            for (int c = 0; c < 4; c++) sa[nt][c] = 0.f;
#pragma unroll
        for (int kc = 0; kc < 4; kc++) {
            const float* qrow = Qs + (kc * 8 + tig) * 136 + w * 16 + g;
            unsigned a0 = fu(qrow[0]);
            unsigned a1 = fu(qrow[8]);
            unsigned a2 = fu(qrow[544]);
            unsigned a3 = fu(qrow[552]);
#pragma unroll
            for (int nt = 0; nt < 8; nt++) {
                unsigned b0 = fu(Ks[(kc * 8 + tig) * 72 + nt * 8 + g]);
                unsigned b1 = fu(Ks[(kc * 8 + tig + 4) * 72 + nt * 8 + g]);
                mma8(sa[nt], a0, a1, a2, a3, b0, b1);
            }
        }
        // + pair bias
#pragma unroll
        for (int nt = 0; nt < 8; nt++) {
            float2 p0 = __half22float2(hp0[nt]);
            float2 p1 = __half22float2(hp1[nt]);
            sa[nt][0] += p0.x; sa[nt][1] += p0.y;
            sa[nt][2] += p1.x; sa[nt][3] += p1.y;
        }
        // online softmax in exp2 domain
        float t0 = -1e30f, t1 = -1e30f;
#pragma unroll
        for (int nt = 0; nt < 8; nt++) {
            t0 = fmaxf(t0, fmaxf(sa[nt][0], sa[nt][1]));
            t1 = fmaxf(t1, fmaxf(sa[nt][2], sa[nt][3]));
        }
        t0 = fmaxf(t0, __shfl_xor_sync(0xffffffffu, t0, 1));
        t0 = fmaxf(t0, __shfl_xor_sync(0xffffffffu, t0, 2));
        t1 = fmaxf(t1, __shfl_xor_sync(0xffffffffu, t1, 1));
        t1 = fmaxf(t1, __shfl_xor_sync(0xffffffffu, t1, 2));
        float mn0 = fmaxf(mrow0, t0), mn1 = fmaxf(mrow1, t1);
        float corr0 = ex2(mrow0 - mn0), corr1 = ex2(mrow1 - mn1);
        mrow0 = mn0; mrow1 = mn1;
        float l0 = 0.f, l1 = 0.f;
#pragma unroll
        for (int nt = 0; nt < 8; nt++) {
            sa[nt][0] = ex2(sa[nt][0] - mn0); l0 += sa[nt][0];
            sa[nt][1] = ex2(sa[nt][1] - mn0); l0 += sa[nt][1];
            sa[nt][2] = ex2(sa[nt][2] - mn1); l1 += sa[nt][2];
            sa[nt][3] = ex2(sa[nt][3] - mn1); l1 += sa[nt][3];
        }
        l0 += __shfl_xor_sync(0xffffffffu, l0, 1);
        l0 += __shfl_xor_sync(0xffffffffu, l0, 2);
        l1 += __shfl_xor_sync(0xffffffffu, l1, 1);
        l1 += __shfl_xor_sync(0xffffffffu, l1, 2);
        lsum0 = lsum0 * corr0 + l0;
        lsum1 = lsum1 * corr1 + l1;
#pragma unroll
        for (int nt = 0; nt < 4; nt++) {
            oacc[nt][0] *= corr0; oacc[nt][1] *= corr0;
            oacc[nt][2] *= corr1; oacc[nt][3] *= corr1;
        }

        // O += P @ V ; P A-frags via shuffles, RNA-rounded to tf32
        const int sl = g * 4 + (tig >> 1);
        const bool odd = tig & 1;
#pragma unroll
        for (int kc = 0; kc < 8; kc++) {
            float p0 = sa[kc][0], p1 = sa[kc][1], p2 = sa[kc][2], p3 = sa[kc][3];
            float u0 = __shfl_sync(0xffffffffu, p0, sl);
            float u1 = __shfl_sync(0xffffffffu, p1, sl);
            float u2 = __shfl_sync(0xffffffffu, p2, sl);
            float u3 = __shfl_sync(0xffffffffu, p3, sl);
            float v0 = __shfl_sync(0xffffffffu, p0, sl + 2);
            float v1 = __shfl_sync(0xffffffffu, p1, sl + 2);
            float v2 = __shfl_sync(0xffffffffu, p2, sl + 2);
            float v3 = __shfl_sync(0xffffffffu, p3, sl + 2);
            unsigned a0 = f2tf(odd ? u1 : u0);
            unsigned a1 = f2tf(odd ? u3 : u2);
            unsigned a2 = f2tf(odd ? v1 : v0);
            unsigned a3 = f2tf(odd ? v3 : v2);
#pragma unroll
            for (int nt = 0; nt < 4; nt++) {
                unsigned b0 = fu(Vs[(nt * 8 + g) * 76 + kc * 8 + tig]);
                unsigned b1 = fu(Vs[(nt * 8 + g) * 76 + kc * 8 + tig + 4]);
                mma8(oacc[nt], a0, a1, a2, a3, b0, b1);
            }
        }
    }

    // epilogue: normalize, gate (g fp32), store tf32 bits to g_att[m][h*32+d]
    float inv0 = 1.f / lsum0, inv1 = 1.f / lsum1;
    int tg0 = i0 + w * 16 + g, tg1 = tg0 + 8;
#pragma unroll
    for (int nt = 0; nt < 4; nt++) {
        int d = nt * 8 + 2 * tig;
        const float* gq0 = g_qkvT + (size_t)(d * 32 + 24 + h) * MTOT + b * NT;
        const float* gq1 = g_qkvT + (size_t)((d + 1) * 32 + 24 + h) * MTOT + b * NT;
        float gv00 = gq0[tg0], gv01 = gq1[tg0];
        float gv10 = gq0[tg1], gv11 = gq1[tg1];
        float2 o0, o1;
        o0.x = __uint_as_float(f2tf(oacc[nt][0] * inv0 * (1.f / (1.f + __expf(-gv00)))));
        o0.y = __uint_as_float(f2tf(oacc[nt][1] * inv0 * (1.f / (1.f + __expf(-gv01)))));
        o1.x = __uint_as_float(f2tf(oacc[nt][2] * inv1 * (1.f / (1.f + __expf(-gv10)))));
        o1.y = __uint_as_float(f2tf(oacc[nt][3] * inv1 * (1.f / (1.f + __expf(-gv11)))));
        *(float2*)&g_att[((size_t)b * NT + tg0) * CM + h * 32 + d] = o0;
        *(float2*)&g_att[((size_t)b * NT + tg1) * CM + h * 32 + d] = o1;
    }
}

// ============================================================
// K4: out = g_att @ W0  (M=4096,K=256,N=256), 64x64 tile
// ============================================================
__global__ void __launch_bounds__(256) out_kernel(const float* __restrict__ W0,
                                                  float* __restrict__ out) {
    __shared__ __align__(16) unsigned As[64 * 36];
    __shared__ __align__(16) unsigned Bs[32 * 72];
    const int tid = threadIdx.x;
    const int warp = tid >> 5, lane = tid & 31;
    const int g = lane >> 2, tig = lane & 3;
    const int wm = warp >> 2, wn = warp & 3;
    const int m0 = blockIdx.x * 64, n0 = blockIdx.y * 64;

    float acc[2][2][4];
#pragma unroll
    for (int i = 0; i < 2; i++)
#pragma unroll
        for (int j = 0; j < 2; j++)
#pragma unroll
            for (int c = 0; c < 4; c++) acc[i][j][c] = 0.f;

    for (int k0 = 0; k0 < CM; k0 += 32) {
        __syncthreads();
        {   // A: raw tf32 bits (g_att pre-rounded)
#pragma unroll
            for (int p = 0; p < 2; p++) {
                int idx = tid + p * 256;
                int row = idx >> 3, c4 = (idx & 7) * 4;
                *(uint4*)(As + row * 36 + c4) =
                    *(const uint4*)(g_att + (size_t)(m0 + row) * CM + k0 + c4);
            }
        }
        {   // B: W0, RNA-rounded to tf32
#pragma unroll
            for (int p = 0; p < 2; p++) {
                int idx = tid + p * 256;
                int row = idx >> 4, c4 = (idx & 15) * 4;
                float4 v = *(const float4*)(W0 + (size_t)(k0 + row) * CM + n0 + c4);
                unsigned* dst = Bs + row * 72 + c4;
                dst[0] = f2tf(v.x); dst[1] = f2tf(v.y);
                dst[2] = f2tf(v.z); dst[3] = f2tf(v.w);
            }
        }
        __syncthreads();
#pragma unroll
        for (int kc = 0; kc < 4; kc++) {
            unsigned a[2][4];
#pragma unroll
            for (int mt = 0; mt < 2; mt++) {
                int r = wm * 32 + mt * 16;
                a[mt][0] = As[(r + g) * 36 + kc * 8 + tig];
                a[mt][1] = As[(r + g + 8) * 36 + kc * 8 + tig];
                a[mt][2] = As[(r + g) * 36 + kc * 8 + tig + 4];
                a[mt][3] = As[(r + g + 8) * 36 + kc * 8 + tig + 4];
            }
#pragma unroll
            for (int nt = 0; nt < 2; nt++) {
                int c = wn * 16 + nt * 8;
                unsigned b0 = Bs[(kc * 8 + tig) * 72 + c + g];
                unsigned b1 = Bs[(kc * 8 + tig + 4) * 72 + c + g];
                mma8(acc[0][nt], a[0][0], a[0][1], a[0][2], a[0][3], b0, b1);
                mma8(acc[1][nt], a[1][0], a[1][1], a[1][2], a[1][3], b0, b1);
            }
        }
    }
#pragma unroll
    for (int mt = 0; mt < 2; mt++) {
        int m = m0 + wm * 32 + mt * 16 + g;
#pragma unroll
        for (int nt = 0; nt < 2; nt++) {
            int n = n0 + wn * 16 + nt * 8 + 2 * tig;
            *(float2*)&out[(size_t)m * CM + n]       = make_float2(acc[mt][nt][0], acc[mt][nt][1]);
            *(float2*)&out[(size_t)(m + 8) * CM + n] = make_float2(acc[mt][nt][2], acc[mt][nt][3]);
        }
    }
}

// ============================================================
extern "C" void kernel_launch(void* const* d_in, const int* in_sizes, int n_in,
                              void* d_out, int out_size) {
    (void)in_sizes; (void)n_in; (void)out_size;
    const float* x        = (const float*)d_in[0];
    const float* bias_rep = (const float*)d_in[1];
    const float* Wqkv     = (const float*)d_in[2];
    const float* W0       = (const float*)d_in[3];
    const float* Wb       = (const float*)d_in[4];
    const float* bb       = (const float*)d_in[5];
    float* out = (float*)d_out;

    cudaFuncSetAttribute(fused1_kernel,
                         cudaFuncAttributeMaxDynamicSharedMemorySize, FUSED_SMEM);
    cudaFuncSetAttribute(attn_kernel,
                         cudaFuncAttributeMaxDynamicSharedMemorySize, ATTN_SMEM);
    fused1_kernel<<<QKV_BLOCKS + 8192, 256, FUSED_SMEM>>>(x, Wqkv, bias_rep, Wb, bb);
    attn_kernel<<<dim3(32, 8), 256, ATTN_SMEM>>>();
    out_kernel<<<dim3(64, 4), 256>>>(W0, out);
}

// round 8
// speedup vs baseline: 4.2881x; 1.0848x over previous
#include <cuda_runtime.h>
#include <cuda_fp16.h>
#include <math.h>

#define NB 4
#define NT 1024
#define CM 256
#define NH 8
#define DHD 32
#define MTOT (NB*NT)   // 4096
#define NTSQ (NT*NT)

#define QSCALE (0.17677669529663687f * 1.4426950408889634f)
#define LOG2E  1.4426950408889634f

// ---- scratch (device globals) ----
// [n=1024][m=4096], n = d*32 + kk*8 + h ; q tf32*QSCALE, k tf32, g fp32 (kk==2 slots unused)
__device__ float g_qkvT[(size_t)4*CM*MTOT];
__device__ __half g_vh[(size_t)CM*MTOT];      // v fp16: [(d*8+h)][m]  2 MB
__device__ __half g_pbh[(size_t)NH*NT*NT];    // [h][i*1024+j], * log2e, fp16
__device__ float g_att[(size_t)MTOT*CM];      // [m][h*32+d]    tf32-bit floats

__device__ __forceinline__ unsigned f2tf(float x) {
    unsigned r; asm("cvt.rna.tf32.f32 %0, %1;" : "=r"(r) : "f"(x)); return r;
}
__device__ __forceinline__ unsigned fu(float x) { return __float_as_uint(x); }
__device__ __forceinline__ float ex2(float x) {
    float r; asm("ex2.approx.ftz.f32 %0, %1;" : "=f"(r) : "f"(x)); return r;
}
__device__ __forceinline__ void mma8(float* d, unsigned a0, unsigned a1,
                                     unsigned a2, unsigned a3,
                                     unsigned b0, unsigned b1) {
    asm("mma.sync.aligned.m16n8k8.row.col.f32.tf32.tf32.f32 "
        "{%0,%1,%2,%3}, {%4,%5,%6,%7}, {%8,%9}, {%0,%1,%2,%3};"
        : "+f"(d[0]), "+f"(d[1]), "+f"(d[2]), "+f"(d[3])
        : "r"(a0), "r"(a1), "r"(a2), "r"(a3), "r"(b0), "r"(b1));
}
__device__ __forceinline__ void mma16h(float* d, unsigned a0, unsigned a1,
                                       unsigned a2, unsigned a3,
                                       unsigned b0, unsigned b1) {
    asm("mma.sync.aligned.m16n8k16.row.col.f32.f16.f16.f32 "
        "{%0,%1,%2,%3}, {%4,%5,%6,%7}, {%8,%9}, {%0,%1,%2,%3};"
        : "+f"(d[0]), "+f"(d[1]), "+f"(d[2]), "+f"(d[3])
        : "r"(a0), "r"(a1), "r"(a2), "r"(a3), "r"(b0), "r"(b1));
}
__device__ __forceinline__ void cpa16(void* dst, const void* src) {
    unsigned s = (unsigned)__cvta_generic_to_shared(dst);
    asm volatile("cp.async.cg.shared.global [%0], [%1], 16;" :: "r"(s), "l"(src));
}
#define CP_COMMIT asm volatile("cp.async.commit_group;")
#define CP_WAIT0  asm volatile("cp.async.wait_group 0;")
#define CP_WAIT1  asm volatile("cp.async.wait_group 1;")

#define QKV_BLOCKS 512
#define FUSED_SMEM 67584   // max(qkv 33792, bias 8 warps * 16*132*4 = 67584)
#define ATTN_SMEM  45056

// ============================================================
// K1 fused: blocks [0,512) -> qkv GEMM ; blocks [512,8704) -> pair-bias
// ============================================================
__global__ void __launch_bounds__(256) fused1_kernel(const float* __restrict__ x,
                                                     const float* __restrict__ Wqkv,
                                                     const float* __restrict__ bias_rep,
                                                     const float* __restrict__ Wb,
                                                     const float* __restrict__ bb) {
    extern __shared__ __align__(16) unsigned char smem_raw[];
    const int tid = threadIdx.x;
    const int warp = tid >> 5, lane = tid & 31;
    const int g = lane >> 2, tig = lane & 3;

    if (blockIdx.x < QKV_BLOCKS) {
        // ---------------- qkv role ----------------
        float* As = (float*)smem_raw;              // [128][36]
        float* Bs = As + 128 * 36;                 // [32][72]
        float* Ts = (float*)smem_raw;              // epilogue [64][132]
        const int wm = warp >> 1, wn = warp & 1;
        const int m0 = ((int)blockIdx.x & 31) * 128;
        const int n0 = ((int)blockIdx.x >> 5) * 64;

        float acc[2][4][4];
#pragma unroll
        for (int i = 0; i < 2; i++)
#pragma unroll
            for (int j = 0; j < 4; j++)
#pragma unroll
                for (int c = 0; c < 4; c++) acc[i][j][c] = 0.f;

        for (int k0 = 0; k0 < CM; k0 += 32) {
            __syncthreads();
            {
                int row = tid >> 1, half = tid & 1;
#pragma unroll
                for (int q = 0; q < 4; q++)
                    cpa16(As + row * 36 + half * 16 + q * 4,
                          x + (size_t)(m0 + row) * CM + k0 + half * 16 + q * 4);
            }
            {
#pragma unroll
                for (int p = 0; p < 2; p++) {
                    int row = (tid >> 4) + p * 16, c4 = (tid & 15) * 4;
                    cpa16(Bs + row * 72 + c4,
                          Wqkv + (size_t)(k0 + row) * 1024 + n0 + c4);
                }
            }
            CP_COMMIT; CP_WAIT0;
            __syncthreads();
#pragma unroll
            for (int kc = 0; kc < 4; kc++) {
                unsigned a[2][4];
#pragma unroll
                for (int mt = 0; mt < 2; mt++) {
                    int r = wm * 32 + mt * 16;
                    a[mt][0] = f2tf(As[(r + g) * 36 + kc * 8 + tig]);
                    a[mt][1] = f2tf(As[(r + g + 8) * 36 + kc * 8 + tig]);
                    a[mt][2] = f2tf(As[(r + g) * 36 + kc * 8 + tig + 4]);
                    a[mt][3] = f2tf(As[(r + g + 8) * 36 + kc * 8 + tig + 4]);
                }
#pragma unroll
                for (int nt = 0; nt < 4; nt++) {
                    int c = wn * 32 + nt * 8;
                    unsigned b0 = f2tf(Bs[(kc * 8 + tig) * 72 + c + g]);
                    unsigned b1 = f2tf(Bs[(kc * 8 + tig + 4) * 72 + c + g]);
                    mma8(acc[0][nt], a[0][0], a[0][1], a[0][2], a[0][3], b0, b1);
                    mma8(acc[1][nt], a[1][0], a[1][1], a[1][2], a[1][3], b0, b1);
                }
            }
        }
        __syncthreads();
#pragma unroll
        for (int mt = 0; mt < 2; mt++) {
            int r = wm * 32 + mt * 16 + g;
#pragma unroll
            for (int nt = 0; nt < 4; nt++) {
                int c = wn * 32 + nt * 8 + 2 * tig;
                Ts[c * 132 + r]           = acc[mt][nt][0];
                Ts[(c + 1) * 132 + r]     = acc[mt][nt][1];
                Ts[c * 132 + r + 8]       = acc[mt][nt][2];
                Ts[(c + 1) * 132 + r + 8] = acc[mt][nt][3];
            }
        }
        __syncthreads();
        {
            int col = tid >> 2, q = tid & 3;
            int n = n0 + col;
            int d = n >> 5, rr = n & 31;
            int kk = rr >> 3, h = rr & 7;
            const float* srcT = Ts + col * 132 + q * 32;
            if (kk == 2) {
                // v -> fp16 g_vh[(d*8+h)][m]
                __half* dst = g_vh + (size_t)(d * 8 + h) * MTOT + m0 + q * 32;
#pragma unroll
                for (int i = 0; i < 4; i++) {
                    float4 v0 = *(const float4*)(srcT + i * 8);
                    float4 v1 = *(const float4*)(srcT + i * 8 + 4);
                    __half2 h0 = __floats2half2_rn(v0.x, v0.y);
                    __half2 h1 = __floats2half2_rn(v0.z, v0.w);
                    __half2 h2 = __floats2half2_rn(v1.x, v1.y);
                    __half2 h3 = __floats2half2_rn(v1.z, v1.w);
                    uint4 o = make_uint4(*(unsigned*)&h0, *(unsigned*)&h1,
                                         *(unsigned*)&h2, *(unsigned*)&h3);
                    *(uint4*)(dst + i * 8) = o;
                }
            } else {
                float* dst = g_qkvT + (size_t)n * MTOT + m0 + q * 32;
                if (kk == 3) {
#pragma unroll
                    for (int i = 0; i < 8; i++)
                        *(float4*)(dst + i * 4) = *(const float4*)(srcT + i * 4);
                } else {
                    float sc = (kk == 0) ? QSCALE : 1.0f;
#pragma unroll
                    for (int i = 0; i < 8; i++) {
                        float4 v = *(const float4*)(srcT + i * 4);
                        float4 o;
                        o.x = __uint_as_float(f2tf(v.x * sc));
                        o.y = __uint_as_float(f2tf(v.y * sc));
                        o.z = __uint_as_float(f2tf(v.z * sc));
                        o.w = __uint_as_float(f2tf(v.w * sc));
                        *(float4*)(dst + i * 4) = o;
                    }
                }
            }
        }
    } else {
        // ---------------- bias role: per-warp pipelined, no block barrier ----------------
        float* As = (float*)smem_raw + warp * (16 * 132);   // this warp's [16][132]
        const int bid = (int)blockIdx.x - QKV_BLOCKS;       // 0..8191
        const int bi = bid >> 3;                            // i
        const int j0 = (bid & 7) * 128 + warp * 16;         // this warp's 16 rows

        unsigned wb0[16], wb1[16];
#pragma unroll
        for (int kc = 0; kc < 16; kc++) {
            wb0[kc] = f2tf(__ldg(&Wb[(kc * 8 + tig) * 8 + g]));
            wb1[kc] = f2tf(__ldg(&Wb[(kc * 8 + tig + 4) * 8 + g]));
        }
        float bbv0 = __ldg(&bb[2 * tig]);
        float bbv1 = __ldg(&bb[2 * tig + 1]);

        const float* src = bias_rep + ((size_t)bi * NT + j0) * 128;
        // group A: columns [0,64) of all 16 rows  (8 chunks/lane)
#pragma unroll
        for (int p = 0; p < 8; p++) {
            int idx = lane + p * 32;                // 0..255
            int row = idx >> 4, c4 = (idx & 15) * 4;
            cpa16(As + row * 132 + c4, src + (size_t)row * 128 + c4);
        }
        CP_COMMIT;
        // group B: columns [64,128)
#pragma unroll
        for (int p = 0; p < 8; p++) {
            int idx = lane + p * 32;
            int row = idx >> 4, c4 = (idx & 15) * 4 + 64;
            cpa16(As + row * 132 + c4, src + (size_t)row * 128 + c4);
        }
        CP_COMMIT;

        float dd[4] = {0.f, 0.f, 0.f, 0.f};
        CP_WAIT1;  __syncwarp();
#pragma unroll
        for (int kc = 0; kc < 8; kc++) {
            unsigned a0 = f2tf(As[g * 132 + kc * 8 + tig]);
            unsigned a1 = f2tf(As[(g + 8) * 132 + kc * 8 + tig]);
            unsigned a2 = f2tf(As[g * 132 + kc * 8 + tig + 4]);
            unsigned a3 = f2tf(As[(g + 8) * 132 + kc * 8 + tig + 4]);
            mma8(dd, a0, a1, a2, a3, wb0[kc], wb1[kc]);
        }
        CP_WAIT0;  __syncwarp();
#pragma unroll
        for (int kc = 8; kc < 16; kc++) {
            unsigned a0 = f2tf(As[g * 132 + kc * 8 + tig]);
            unsigned a1 = f2tf(As[(g + 8) * 132 + kc * 8 + tig]);
            unsigned a2 = f2tf(As[g * 132 + kc * 8 + tig + 4]);
            unsigned a3 = f2tf(As[(g + 8) * 132 + kc * 8 + tig + 4]);
            mma8(dd, a0, a1, a2, a3, wb0[kc], wb1[kc]);
        }
        size_t m = (size_t)bi * NT + j0 + g;
        g_pbh[(size_t)(2 * tig) * NTSQ     + m]     = __float2half((dd[0] + bbv0) * LOG2E);
        g_pbh[(size_t)(2 * tig + 1) * NTSQ + m]     = __float2half((dd[1] + bbv1) * LOG2E);
        g_pbh[(size_t)(2 * tig) * NTSQ     + m + 8] = __float2half((dd[2] + bbv0) * LOG2E);
        g_pbh[(size_t)(2 * tig + 1) * NTSQ + m + 8] = __float2half((dd[3] + bbv1) * LOG2E);
    }
}

// ============================================================
// K3: flash attention; S: tf32 HMMA; PV: fp16 HMMA (no shuffles)
// 256 thr = 8 warps; block = (b,h) x 128 q-rows
// ============================================================
__global__ void __launch_bounds__(256, 3) attn_kernel() {
    extern __shared__ float asmem[];
    float* Qs = asmem;                        // [32][136] fp32
    float* Ksb0 = asmem + 4352;               // [32][72]  fp32
    float* Ksb1 = asmem + 6656;
    __half* Vsb0 = (__half*)(asmem + 8960);   // [32][72]  half
    __half* Vsb1 = (__half*)(asmem + 10112);

    const int bh = blockIdx.x;
    const int b = bh >> 3, h = bh & 7;
    const int i0 = blockIdx.y * 128;
    const int tid = threadIdx.x;
    const int w = tid >> 5, lane = tid & 31;
    const int g = lane >> 2, tig = lane & 3;

    // stage Q (once)
#pragma unroll
    for (int r = 0; r < 4; r++) {
        int c = tid + r * 256;
        int d = c >> 5, c4 = (c & 31) * 4;
        cpa16(Qs + d * 136 + c4,
              g_qkvT + (size_t)(d * 32 + h) * MTOT + b * NT + i0 + c4);
    }
    // stage K/V tile 0
#pragma unroll
    for (int r = 0; r < 2; r++) {
        int c = tid + r * 256;
        int d = c >> 4, c4 = (c & 15) * 4;
        cpa16(Ksb0 + d * 72 + c4, g_qkvT + (size_t)(d * 32 + 8 + h) * MTOT + b * NT + c4);
    }
    {
        int d = tid >> 3, c8 = (tid & 7) * 8;
        cpa16(Vsb0 + d * 72 + c8, g_vh + (size_t)(d * 8 + h) * MTOT + b * NT + c8);
    }
    CP_COMMIT;

    float oacc[4][4];
#pragma unroll
    for (int i = 0; i < 4; i++)
#pragma unroll
        for (int c = 0; c < 4; c++) oacc[i][c] = 0.f;
    float mrow0 = -1e30f, mrow1 = -1e30f, lsum0 = 0.f, lsum1 = 0.f;

    const __half* pb0 = g_pbh + (size_t)h * NTSQ + (size_t)(i0 + w * 16 + g) * NT;
    const __half* pb1 = pb0 + 8 * NT;

    for (int n = 0; n < 16; n++) {
        CP_WAIT0;
        __syncthreads();
        const float* Ks = (n & 1) ? Ksb1 : Ksb0;
        const __half* Vs = (n & 1) ? Vsb1 : Vsb0;
        if (n < 15) {
            float* Kd = (n & 1) ? Ksb0 : Ksb1;
            __half* Vd = (n & 1) ? Vsb0 : Vsb1;
            int jn = (n + 1) * 64;
#pragma unroll
            for (int r = 0; r < 2; r++) {
                int c = tid + r * 256;
                int d = c >> 4, c4 = (c & 15) * 4;
                cpa16(Kd + d * 72 + c4,
                      g_qkvT + (size_t)(d * 32 + 8 + h) * MTOT + b * NT + jn + c4);
            }
            {
                int d = tid >> 3, c8 = (tid & 7) * 8;
                cpa16(Vd + d * 72 + c8,
                      g_vh + (size_t)(d * 8 + h) * MTOT + b * NT + jn + c8);
            }
            CP_COMMIT;
        }
        const int jt = n * 64;

        // prefetch pair bias (fp16) — overlaps S MMAs
        __half2 hp0[8], hp1[8];
#pragma unroll
        for (int nt = 0; nt < 8; nt++) {
            hp0[nt] = *(const __half2*)(pb0 + jt + nt * 8 + 2 * tig);
            hp1[nt] = *(const __half2*)(pb1 + jt + nt * 8 + 2 * tig);
        }

        // S = Q K^T  (tf32)
        float sa[8][4];
#pragma unroll
        for (int nt = 0; nt < 8; nt++)
#pragma unroll
            for (int c = 0; c < 4; c++) sa[nt][c] = 0.f;
#pragma unroll
        for (int kc = 0; kc < 4; kc++) {
            const float* qrow = Qs + (kc * 8 + tig) * 136 + w * 16 + g;
            unsigned a0 = fu(qrow[0]);
            unsigned a1 = fu(qrow[8]);
            unsigned a2 = fu(qrow[544]);
            unsigned a3 = fu(qrow[552]);
#pragma unroll
            for (int nt = 0; nt < 8; nt++) {
                unsigned b0 = fu(Ks[(kc * 8 + tig) * 72 + nt * 8 + g]);
                unsigned b1 = fu(Ks[(kc * 8 + tig + 4) * 72 + nt * 8 + g]);
                mma8(sa[nt], a0, a1, a2, a3, b0, b1);
            }
        }
        // + pair bias
#pragma unroll
        for (int nt = 0; nt < 8; nt++) {
            float2 p0 = __half22float2(hp0[nt]);
            float2 p1 = __half22float2(hp1[nt]);
            sa[nt][0] += p0.x; sa[nt][1] += p0.y;
            sa[nt][2] += p1.x; sa[nt][3] += p1.y;
        }
        // online softmax (exp2 domain)
        float t0 = -1e30f, t1 = -1e30f;
#pragma unroll
        for (int nt = 0; nt < 8; nt++) {
            t0 = fmaxf(t0, fmaxf(sa[nt][0], sa[nt][1]));
            t1 = fmaxf(t1, fmaxf(sa[nt][2], sa[nt][3]));
        }
        t0 = fmaxf(t0, __shfl_xor_sync(0xffffffffu, t0, 1));
        t0 = fmaxf(t0, __shfl_xor_sync(0xffffffffu, t0, 2));
        t1 = fmaxf(t1, __shfl_xor_sync(0xffffffffu, t1, 1));
        t1 = fmaxf(t1, __shfl_xor_sync(0xffffffffu, t1, 2));
        float mn0 = fmaxf(mrow0, t0), mn1 = fmaxf(mrow1, t1);
        float corr0 = ex2(mrow0 - mn0), corr1 = ex2(mrow1 - mn1);
        mrow0 = mn0; mrow1 = mn1;
        float l0 = 0.f, l1 = 0.f;
#pragma unroll
        for (int nt = 0; nt < 8; nt++) {
            sa[nt][0] = ex2(sa[nt][0] - mn0); l0 += sa[nt][0];
            sa[nt][1] = ex2(sa[nt][1] - mn0); l0 += sa[nt][1];
            sa[nt][2] = ex2(sa[nt][2] - mn1); l1 += sa[nt][2];
            sa[nt][3] = ex2(sa[nt][3] - mn1); l1 += sa[nt][3];
        }
        l0 += __shfl_xor_sync(0xffffffffu, l0, 1);
        l0 += __shfl_xor_sync(0xffffffffu, l0, 2);
        l1 += __shfl_xor_sync(0xffffffffu, l1, 1);
        l1 += __shfl_xor_sync(0xffffffffu, l1, 2);
        lsum0 = lsum0 * corr0 + l0;
        lsum1 = lsum1 * corr1 + l1;
#pragma unroll
        for (int nt = 0; nt < 4; nt++) {
            oacc[nt][0] *= corr0; oacc[nt][1] *= corr0;
            oacc[nt][2] *= corr1; oacc[nt][3] *= corr1;
        }

        // O += P @ V  (fp16 mma; P C-frag == fp16 A-frag, no shuffles)
#pragma unroll
        for (int kc = 0; kc < 4; kc++) {
            __half2 h0 = __floats2half2_rn(sa[2 * kc][0],     sa[2 * kc][1]);
            __half2 h1 = __floats2half2_rn(sa[2 * kc][2],     sa[2 * kc][3]);
            __half2 h2 = __floats2half2_rn(sa[2 * kc + 1][0], sa[2 * kc + 1][1]);
            __half2 h3 = __floats2half2_rn(sa[2 * kc + 1][2], sa[2 * kc + 1][3]);
            unsigned a0 = *(unsigned*)&h0, a1 = *(unsigned*)&h1;
            unsigned a2 = *(unsigned*)&h2, a3 = *(unsigned*)&h3;
#pragma unroll
            for (int nt = 0; nt < 4; nt++) {
                unsigned b0 = *(const unsigned*)&Vs[(nt * 8 + g) * 72 + kc * 16 + 2 * tig];
                unsigned b1 = *(const unsigned*)&Vs[(nt * 8 + g) * 72 + kc * 16 + 2 * tig + 8];
                mma16h(oacc[nt], a0, a1, a2, a3, b0, b1);
            }
        }
    }

    // epilogue
    float inv0 = 1.f / lsum0, inv1 = 1.f / lsum1;
    int tg0 = i0 + w * 16 + g, tg1 = tg0 + 8;
#pragma unroll
    for (int nt = 0; nt < 4; nt++) {
        int d = nt * 8 + 2 * tig;
        const float* gq0 = g_qkvT + (size_t)(d * 32 + 24 + h) * MTOT + b * NT;
        const float* gq1 = g_qkvT + (size_t)((d + 1) * 32 + 24 + h) * MTOT + b * NT;
        float gv00 = gq0[tg0], gv01 = gq1[tg0];
        float gv10 = gq0[tg1], gv11 = gq1[tg1];
        float2 o0, o1;
        o0.x = __uint_as_float(f2tf(oacc[nt][0] * inv0 * (1.f / (1.f + __expf(-gv00)))));
        o0.y = __uint_as_float(f2tf(oacc[nt][1] * inv0 * (1.f / (1.f + __expf(-gv01)))));
        o1.x = __uint_as_float(f2tf(oacc[nt][2] * inv1 * (1.f / (1.f + __expf(-gv10)))));
        o1.y = __uint_as_float(f2tf(oacc[nt][3] * inv1 * (1.f / (1.f + __expf(-gv11)))));
        *(float2*)&g_att[((size_t)b * NT + tg0) * CM + h * 32 + d] = o0;
        *(float2*)&g_att[((size_t)b * NT + tg1) * CM + h * 32 + d] = o1;
    }
}

// ============================================================
// K4: out = g_att @ W0  (M=4096,K=256,N=256)
// ============================================================
__global__ void __launch_bounds__(256) out_kernel(const float* __restrict__ W0,
                                                  float* __restrict__ out) {
    __shared__ __align__(16) unsigned As[64 * 36];
    __shared__ __align__(16) unsigned Bs[32 * 72];
    const int tid = threadIdx.x;
    const int warp = tid >> 5, lane = tid & 31;
    const int g = lane >> 2, tig = lane & 3;
    const int wm = warp >> 2, wn = warp & 3;
    const int m0 = blockIdx.x * 64, n0 = blockIdx.y * 64;

    float acc[2][2][4];
#pragma unroll
    for (int i = 0; i < 2; i++)
#pragma unroll
        for (int j = 0; j < 2; j++)
#pragma unroll
            for (int c = 0; c < 4; c++) acc[i][j][c] = 0.f;

    for (int k0 = 0; k0 < CM; k0 += 32) {
        __syncthreads();
        {
#pragma unroll
            for (int p = 0; p < 2; p++) {
                int idx = tid + p * 256;
                int row = idx >> 3, c4 = (idx & 7) * 4;
                *(uint4*)(As + row * 36 + c4) =
                    *(const uint4*)(g_att + (size_t)(m0 + row) * CM + k0 + c4);
            }
        }
        {
#pragma unroll
            for (int p = 0; p < 2; p++) {
                int idx = tid + p * 256;
                int row = idx >> 4, c4 = (idx & 15) * 4;
                float4 v = *(const float4*)(W0 + (size_t)(k0 + row) * CM + n0 + c4);
                unsigned* dst = Bs + row * 72 + c4;
                dst[0] = f2tf(v.x); dst[1] = f2tf(v.y);
                dst[2] = f2tf(v.z); dst[3] = f2tf(v.w);
            }
        }
        __syncthreads();
#pragma unroll
        for (int kc = 0; kc < 4; kc++) {
            unsigned a[2][4];
#pragma unroll
            for (int mt = 0; mt < 2; mt++) {
                int r = wm * 32 + mt * 16;
                a[mt][0] = As[(r + g) * 36 + kc * 8 + tig];
                a[mt][1] = As[(r + g + 8) * 36 + kc * 8 + tig];
                a[mt][2] = As[(r + g) * 36 + kc * 8 + tig + 4];
                a[mt][3] = As[(r + g + 8) * 36 + kc * 8 + tig + 4];
            }
#pragma unroll
            for (int nt = 0; nt < 2; nt++) {
                int c = wn * 16 + nt * 8;
                unsigned b0 = Bs[(kc * 8 + tig) * 72 + c + g];
                unsigned b1 = Bs[(kc * 8 + tig + 4) * 72 + c + g];
                mma8(acc[0][nt], a[0][0], a[0][1], a[0][2], a[0][3], b0, b1);
                mma8(acc[1][nt], a[1][0], a[1][1], a[1][2], a[1][3], b0, b1);
            }
        }
    }
#pragma unroll
    for (int mt = 0; mt < 2; mt++) {
        int m = m0 + wm * 32 + mt * 16 + g;
#pragma unroll
        for (int nt = 0; nt < 2; nt++) {
            int n = n0 + wn * 16 + nt * 8 + 2 * tig;
            *(float2*)&out[(size_t)m * CM + n]       = make_float2(acc[mt][nt][0], acc[mt][nt][1]);
            *(float2*)&out[(size_t)(m + 8) * CM + n] = make_float2(acc[mt][nt][2], acc[mt][nt][3]);
        }
    }
}

// ============================================================
extern "C" void kernel_launch(void* const* d_in, const int* in_sizes, int n_in,
                              void* d_out, int out_size) {
    (void)in_sizes; (void)n_in; (void)out_size;
    const float* x        = (const float*)d_in[0];
    const float* bias_rep = (const float*)d_in[1];
    const float* Wqkv     = (const float*)d_in[2];
    const float* W0       = (const float*)d_in[3];
    const float* Wb       = (const float*)d_in[4];
    const float* bb       = (const float*)d_in[5];
    float* out = (float*)d_out;

    cudaFuncSetAttribute(fused1_kernel,
                         cudaFuncAttributeMaxDynamicSharedMemorySize, FUSED_SMEM);
    cudaFuncSetAttribute(attn_kernel,
                         cudaFuncAttributeMaxDynamicSharedMemorySize, ATTN_SMEM);
    fused1_kernel<<<QKV_BLOCKS + 8192, 256, FUSED_SMEM>>>(x, Wqkv, bias_rep, Wb, bb);
    attn_kernel<<<dim3(32, 8), 256, ATTN_SMEM>>>();
    out_kernel<<<dim3(64, 4), 256>>>(W0, out);
}